// round 5
// baseline (speedup 1.0000x reference)
#include <cuda_runtime.h>
#include <math.h>

// Problem constants
#define BB   4
#define CC   256
#define C4   64
#define HWN  4096

// Scratch (static device arrays; no allocation)
__device__ float g_q [BB * C4 * HWN];          // [b][c][hw]
__device__ float g_kl[BB * C4 * HWN];          // [b][c][hw]
__device__ float g_kf[BB * C4 * HWN];          // [b][c][hw]
__device__ float g_v [BB * HWN * C4];          // [b][hw][c]  (k-major for GEMM2)
__device__ float g_fused[BB * HWN * 128];      // [b][hw][cf] (cf: 0-63 = out_l, 64-127 = out_f)

// ---------------------------------------------------------------------------
// Kernel 1: projections.  Y = W[64,256] @ X[256,4096] + bias  (per batch, 4 proj)
// grid (32 hw-tiles, B, 4 proj), block 256. Tile 64 rows x 128 cols.
// proj 3 (v) is written transposed to [hw][c].
// ---------------------------------------------------------------------------
__global__ __launch_bounds__(256) void proj_kernel(
    const float* __restrict__ last, const float* __restrict__ cur, const float* __restrict__ fut,
    const float* __restrict__ Wqk, const float* __restrict__ bqk,
    const float* __restrict__ Wkl, const float* __restrict__ bkl,
    const float* __restrict__ Wkf, const float* __restrict__ bkf,
    const float* __restrict__ Wv,  const float* __restrict__ bv)
{
    __shared__ float Ws[32 * 64];    // Ws[k][r]
    __shared__ float Xs[32 * 128];   // Xs[k][col]

    const int tile = blockIdx.x;     // 0..31
    const int b    = blockIdx.y;
    const int p    = blockIdx.z;     // 0..3

    const float* X; const float* W; const float* bias;
    if      (p == 0) { X = cur;  W = Wqk; bias = bqk; }
    else if (p == 1) { X = last; W = Wkl; bias = bkl; }
    else if (p == 2) { X = fut;  W = Wkf; bias = bkf; }
    else             { X = cur;  W = Wv;  bias = bv;  }

    const float* Xb = X + (size_t)b * CC * HWN;
    const int col0 = tile * 128;
    const int t  = threadIdx.x;
    const int ty = t >> 5;           // 0..7  -> rows ty*8..+7
    const int tx = t & 31;           // 0..31 -> cols tx*4..+3

    float acc[8][4];
    #pragma unroll
    for (int i = 0; i < 8; ++i)
        #pragma unroll
        for (int j = 0; j < 4; ++j) acc[i][j] = 0.f;

    for (int kk = 0; kk < CC; kk += 32) {
        // Ws[k][r] = W[r][kk+k]  (transposed load; conflict-free STS: bank = r%32)
        #pragma unroll
        for (int pp = 0; pp < 2; ++pp) {
            int idx = t + pp * 256;          // 0..511
            int r   = idx & 63;
            int k4  = (idx >> 6) * 4;        // 0,4,...,28
            float4 w = *(const float4*)&W[r * 256 + kk + k4];
            Ws[(k4 + 0) * 64 + r] = w.x;
            Ws[(k4 + 1) * 64 + r] = w.y;
            Ws[(k4 + 2) * 64 + r] = w.z;
            Ws[(k4 + 3) * 64 + r] = w.w;
        }
        // Xs[k][col] = X[kk+k][col0+col]  (coalesced float4)
        #pragma unroll
        for (int pp = 0; pp < 4; ++pp) {
            int idx  = t + pp * 256;         // 0..1023 float4 slots
            int k    = idx >> 5;             // 0..31
            int c4   = (idx & 31) * 4;       // 0..124
            *(float4*)&Xs[k * 128 + c4] =
                *(const float4*)&Xb[(size_t)(kk + k) * HWN + col0 + c4];
        }
        __syncthreads();
        #pragma unroll 8
        for (int k = 0; k < 32; ++k) {
            float4 x  = *(const float4*)&Xs[k * 128 + tx * 4];
            float4 w0 = *(const float4*)&Ws[k * 64 + ty * 8];
            float4 w1 = *(const float4*)&Ws[k * 64 + ty * 8 + 4];
            float wr[8] = {w0.x, w0.y, w0.z, w0.w, w1.x, w1.y, w1.z, w1.w};
            float xc[4] = {x.x, x.y, x.z, x.w};
            #pragma unroll
            for (int i = 0; i < 8; ++i)
                #pragma unroll
                for (int j = 0; j < 4; ++j)
                    acc[i][j] += wr[i] * xc[j];
        }
        __syncthreads();
    }

    if (p < 3) {
        float* out = (p == 0 ? g_q : (p == 1 ? g_kl : g_kf)) + (size_t)b * C4 * HWN;
        #pragma unroll
        for (int i = 0; i < 8; ++i) {
            int r = ty * 8 + i;
            float bb = bias[r];
            float4 v = make_float4(acc[i][0] + bb, acc[i][1] + bb,
                                   acc[i][2] + bb, acc[i][3] + bb);
            *(float4*)&out[(size_t)r * HWN + col0 + tx * 4] = v;
        }
    } else {
        // v transposed: g_v[b][hw][c]
        #pragma unroll
        for (int i = 0; i < 8; ++i) {
            int r = ty * 8 + i;
            float bb = bias[r];
            #pragma unroll
            for (int j = 0; j < 4; ++j)
                g_v[((size_t)b * HWN + col0 + tx * 4 + j) * C4 + r] = acc[i][j] + bb;
        }
    }
}

// ---------------------------------------------------------------------------
// Kernel 2: fused flash attention (both sides). grid (64 qtiles, B, 2 sides).
// Per CTA: 64 queries x full 4096 keys in 64-key tiles, online softmax.
// 256 threads: ty=t/16 -> q rows ty*4..+3 ; tx=t%16 -> (S: keys tx*4..+3,
// O: channels tx*4..+3). 16-lane row groups == half warps -> shfl reductions.
// ---------------------------------------------------------------------------
__global__ __launch_bounds__(256) void attn_kernel()
{
    __shared__ float Qs [64 * 64];   // Qs[c][q]
    __shared__ float KPs[64 * 64];   // K tile [c][k], reused as P tile [q][k]
    __shared__ float Vt [64 * 64];   // Vt[k][c]

    const int qt   = blockIdx.x;     // 0..63
    const int b    = blockIdx.y;
    const int side = blockIdx.z;

    const float* Qg = g_q + (size_t)b * C4 * HWN;
    const float* Kg = (side == 0 ? g_kl : g_kf) + (size_t)b * C4 * HWN;
    const float* Vg = g_v + (size_t)b * HWN * C4;

    const int q0 = qt * 64;
    const int t  = threadIdx.x;
    const int ty = t >> 4;           // 0..15
    const int tx = t & 15;           // 0..15

    #pragma unroll
    for (int pp = 0; pp < 4; ++pp) {
        int idx = t + pp * 256;      // float4 slots
        int c   = idx >> 4;
        int q4  = (idx & 15) * 4;
        *(float4*)&Qs[c * 64 + q4] = *(const float4*)&Qg[(size_t)c * HWN + q0 + q4];
    }

    float m_run[4], l_run[4], o[4][4];
    #pragma unroll
    for (int i = 0; i < 4; ++i) {
        m_run[i] = -INFINITY; l_run[i] = 0.f;
        #pragma unroll
        for (int j = 0; j < 4; ++j) o[i][j] = 0.f;
    }

    for (int k0 = 0; k0 < HWN; k0 += 64) {
        __syncthreads();   // protect KPs/Vt from previous iteration readers (covers Q load on iter 0)
        #pragma unroll
        for (int pp = 0; pp < 4; ++pp) {
            int idx = t + pp * 256;
            int c   = idx >> 4;
            int k4  = (idx & 15) * 4;
            *(float4*)&KPs[c * 64 + k4] = *(const float4*)&Kg[(size_t)c * HWN + k0 + k4];
        }
        #pragma unroll
        for (int pp = 0; pp < 4; ++pp) {
            int idx = t + pp * 256;
            int kk  = idx >> 4;
            int c4  = (idx & 15) * 4;
            *(float4*)&Vt[kk * 64 + c4] = *(const float4*)&Vg[(size_t)(k0 + kk) * C4 + c4];
        }
        __syncthreads();

        // GEMM1: S[q][k] = sum_c Q[c][q] * K[c][k]
        float s[4][4];
        #pragma unroll
        for (int i = 0; i < 4; ++i)
            #pragma unroll
            for (int j = 0; j < 4; ++j) s[i][j] = 0.f;

        #pragma unroll 8
        for (int c = 0; c < 64; ++c) {
            float4 qv = *(const float4*)&Qs [c * 64 + ty * 4];
            float4 kv = *(const float4*)&KPs[c * 64 + tx * 4];
            float qa[4] = {qv.x, qv.y, qv.z, qv.w};
            float ka[4] = {kv.x, kv.y, kv.z, kv.w};
            #pragma unroll
            for (int i = 0; i < 4; ++i)
                #pragma unroll
                for (int j = 0; j < 4; ++j)
                    s[i][j] += qa[i] * ka[j];
        }

        // online softmax per q-row (reduce across 16 lanes = half warp)
        float alpha[4];
        #pragma unroll
        for (int i = 0; i < 4; ++i) {
            float tm = fmaxf(fmaxf(s[i][0], s[i][1]), fmaxf(s[i][2], s[i][3]));
            #pragma unroll
            for (int off = 8; off > 0; off >>= 1)
                tm = fmaxf(tm, __shfl_xor_sync(0xffffffffu, tm, off));
            float nm = fmaxf(m_run[i], tm);
            alpha[i] = __expf(m_run[i] - nm);
            m_run[i] = nm;
            float rs = 0.f;
            #pragma unroll
            for (int j = 0; j < 4; ++j) { s[i][j] = __expf(s[i][j] - nm); rs += s[i][j]; }
            #pragma unroll
            for (int off = 8; off > 0; off >>= 1)
                rs += __shfl_xor_sync(0xffffffffu, rs, off);
            l_run[i] = l_run[i] * alpha[i] + rs;
            #pragma unroll
            for (int j = 0; j < 4; ++j) o[i][j] *= alpha[i];
        }

        __syncthreads();   // everyone done reading KPs as K
        #pragma unroll
        for (int i = 0; i < 4; ++i)
            *(float4*)&KPs[(ty * 4 + i) * 64 + tx * 4] =
                make_float4(s[i][0], s[i][1], s[i][2], s[i][3]);
        __syncthreads();

        // GEMM2: O[q][c] += sum_k P[q][k] * V[k][c]
        #pragma unroll 8
        for (int k = 0; k < 64; ++k) {
            float4 vv = *(const float4*)&Vt[k * 64 + tx * 4];
            float p0 = KPs[(ty * 4 + 0) * 64 + k];
            float p1 = KPs[(ty * 4 + 1) * 64 + k];
            float p2 = KPs[(ty * 4 + 2) * 64 + k];
            float p3 = KPs[(ty * 4 + 3) * 64 + k];
            float va[4] = {vv.x, vv.y, vv.z, vv.w};
            float pa[4] = {p0, p1, p2, p3};
            #pragma unroll
            for (int i = 0; i < 4; ++i)
                #pragma unroll
                for (int j = 0; j < 4; ++j)
                    o[i][j] += pa[i] * va[j];
        }
    }

    // epilogue: normalize, write g_fused[b][hw][cf]
    #pragma unroll
    for (int i = 0; i < 4; ++i) {
        float invl = 1.f / l_run[i];
        float4 r = make_float4(o[i][0] * invl, o[i][1] * invl,
                               o[i][2] * invl, o[i][3] * invl);
        *(float4*)&g_fused[((size_t)b * HWN + q0 + ty * 4 + i) * 128 + side * 64 + tx * 4] = r;
    }
}

// ---------------------------------------------------------------------------
// Kernel 3: fire conv + BN + residual + ReLU.
// fired = Wfire[256,128] @ fused[128,4096]; out = relu(cur + fired*inv + shift)
// grid (32 hw-tiles, 4 row-tiles, B), block 256. Tile 64 rows x 128 cols, K=128.
// ---------------------------------------------------------------------------
__global__ __launch_bounds__(256) void fire_kernel(
    const float* __restrict__ cur,
    const float* __restrict__ Wfire, const float* __restrict__ bfire,
    const float* __restrict__ gamma, const float* __restrict__ beta,
    const float* __restrict__ mean,  const float* __restrict__ var,
    float* __restrict__ out)
{
    __shared__ float Ws[32 * 64];     // Ws[k][r]
    __shared__ float Xs[32 * 132];    // Xs[k][col], pitch 132 (float4-readable)

    const int tile = blockIdx.x;      // 0..31
    const int rt   = blockIdx.y;      // 0..3
    const int b    = blockIdx.z;
    const int r0   = rt * 64;
    const int col0 = tile * 128;
    const int t  = threadIdx.x;
    const int ty = t >> 5;
    const int tx = t & 31;

    const float* Fb = g_fused + (size_t)b * HWN * 128;

    float acc[8][4];
    #pragma unroll
    for (int i = 0; i < 8; ++i)
        #pragma unroll
        for (int j = 0; j < 4; ++j) acc[i][j] = 0.f;

    for (int kk = 0; kk < 128; kk += 32) {
        #pragma unroll
        for (int pp = 0; pp < 2; ++pp) {
            int idx = t + pp * 256;
            int r   = idx & 63;
            int k4  = (idx >> 6) * 4;
            float4 w = *(const float4*)&Wfire[(r0 + r) * 128 + kk + k4];
            Ws[(k4 + 0) * 64 + r] = w.x;
            Ws[(k4 + 1) * 64 + r] = w.y;
            Ws[(k4 + 2) * 64 + r] = w.z;
            Ws[(k4 + 3) * 64 + r] = w.w;
        }
        // transpose-load fused[hw-major] into Xs[k][col]
        #pragma unroll
        for (int pp = 0; pp < 4; ++pp) {
            int idx = t + pp * 256;          // 0..1023
            int col = idx >> 3;              // 0..127
            int k4  = (idx & 7) * 4;         // 0..28
            float4 x = *(const float4*)&Fb[(size_t)(col0 + col) * 128 + kk + k4];
            Xs[(k4 + 0) * 132 + col] = x.x;
            Xs[(k4 + 1) * 132 + col] = x.y;
            Xs[(k4 + 2) * 132 + col] = x.z;
            Xs[(k4 + 3) * 132 + col] = x.w;
        }
        __syncthreads();
        #pragma unroll 8
        for (int k = 0; k < 32; ++k) {
            float4 x  = *(const float4*)&Xs[k * 132 + tx * 4];
            float4 w0 = *(const float4*)&Ws[k * 64 + ty * 8];
            float4 w1 = *(const float4*)&Ws[k * 64 + ty * 8 + 4];
            float wr[8] = {w0.x, w0.y, w0.z, w0.w, w1.x, w1.y, w1.z, w1.w};
            float xc[4] = {x.x, x.y, x.z, x.w};
            #pragma unroll
            for (int i = 0; i < 8; ++i)
                #pragma unroll
                for (int j = 0; j < 4; ++j)
                    acc[i][j] += wr[i] * xc[j];
        }
        __syncthreads();
    }

    const float* curb = cur + (size_t)b * CC * HWN;
    #pragma unroll
    for (int i = 0; i < 8; ++i) {
        int r = r0 + ty * 8 + i;
        float inv   = gamma[r] * rsqrtf(var[r] + 1e-5f);
        float shift = beta[r] - mean[r] * inv;
        float bb    = bfire[r];
        size_t base = (size_t)r * HWN + col0 + tx * 4;
        float4 c4 = *(const float4*)&curb[base];
        float4 rv;
        rv.x = fmaxf(c4.x + (acc[i][0] + bb) * inv + shift, 0.f);
        rv.y = fmaxf(c4.y + (acc[i][1] + bb) * inv + shift, 0.f);
        rv.z = fmaxf(c4.z + (acc[i][2] + bb) * inv + shift, 0.f);
        rv.w = fmaxf(c4.w + (acc[i][3] + bb) * inv + shift, 0.f);
        *(float4*)&out[(size_t)b * CC * HWN + base] = rv;
    }
}

// ---------------------------------------------------------------------------
extern "C" void kernel_launch(void* const* d_in, const int* in_sizes, int n_in,
                              void* d_out, int out_size)
{
    const float* last  = (const float*)d_in[0];
    const float* cur   = (const float*)d_in[1];
    const float* fut   = (const float*)d_in[2];
    const float* Wqk   = (const float*)d_in[3];
    const float* bqk   = (const float*)d_in[4];
    const float* Wkl   = (const float*)d_in[5];
    const float* bkl   = (const float*)d_in[6];
    const float* Wkf   = (const float*)d_in[7];
    const float* bkf   = (const float*)d_in[8];
    const float* Wv    = (const float*)d_in[9];
    const float* bv    = (const float*)d_in[10];
    const float* Wfire = (const float*)d_in[11];
    const float* bfire = (const float*)d_in[12];
    const float* gamma = (const float*)d_in[13];
    const float* beta  = (const float*)d_in[14];
    const float* mean  = (const float*)d_in[15];
    const float* var   = (const float*)d_in[16];

    proj_kernel<<<dim3(32, BB, 4), 256>>>(last, cur, fut,
                                          Wqk, bqk, Wkl, bkl, Wkf, bkf, Wv, bv);
    attn_kernel<<<dim3(64, BB, 2), 256>>>();
    fire_kernel<<<dim3(32, 4, BB), 256>>>(cur, Wfire, bfire,
                                          gamma, beta, mean, var, (float*)d_out);
}

// round 6
// speedup vs baseline: 1.0579x; 1.0579x over previous
#include <cuda_runtime.h>
#include <math.h>

// Problem constants
#define BB   4
#define CC   256
#define C4   64
#define HWN  4096

// Scratch (static device arrays; no allocation)
__device__ float g_q [BB * C4 * HWN];          // [b][c][hw]
__device__ float g_kl[BB * C4 * HWN];          // [b][c][hw]
__device__ float g_kf[BB * C4 * HWN];          // [b][c][hw]
__device__ float g_v [BB * HWN * C4];          // [b][hw][c]  (k-major for GEMM2)
__device__ float g_fused[BB * HWN * 128];      // [b][hw][cf] (cf: 0-63 = out_l, 64-127 = out_f)

// ---------------------------------------------------------------------------
// Kernel 1: projections.  Y = W[64,256] @ X[256,4096] + bias  (per batch, 4 proj)
// grid (32 hw-tiles, B, 4 proj), block 256. Tile 64 rows x 128 cols.
// proj 3 (v) is written transposed to [hw][c].
// ---------------------------------------------------------------------------
__global__ __launch_bounds__(256) void proj_kernel(
    const float* __restrict__ last, const float* __restrict__ cur, const float* __restrict__ fut,
    const float* __restrict__ Wqk, const float* __restrict__ bqk,
    const float* __restrict__ Wkl, const float* __restrict__ bkl,
    const float* __restrict__ Wkf, const float* __restrict__ bkf,
    const float* __restrict__ Wv,  const float* __restrict__ bv)
{
    __shared__ float Ws[32 * 64];    // Ws[k][r]
    __shared__ float Xs[32 * 128];   // Xs[k][col]

    const int tile = blockIdx.x;     // 0..31
    const int b    = blockIdx.y;
    const int p    = blockIdx.z;     // 0..3

    const float* X; const float* W; const float* bias;
    if      (p == 0) { X = cur;  W = Wqk; bias = bqk; }
    else if (p == 1) { X = last; W = Wkl; bias = bkl; }
    else if (p == 2) { X = fut;  W = Wkf; bias = bkf; }
    else             { X = cur;  W = Wv;  bias = bv;  }

    const float* Xb = X + (size_t)b * CC * HWN;
    const int col0 = tile * 128;
    const int t  = threadIdx.x;
    const int ty = t >> 5;           // 0..7  -> rows ty*8..+7
    const int tx = t & 31;           // 0..31 -> cols tx*4..+3

    float acc[8][4];
    #pragma unroll
    for (int i = 0; i < 8; ++i)
        #pragma unroll
        for (int j = 0; j < 4; ++j) acc[i][j] = 0.f;

    for (int kk = 0; kk < CC; kk += 32) {
        // Ws[k][r] = W[r][kk+k]  (transposed load; conflict-free STS: bank = r%32)
        #pragma unroll
        for (int pp = 0; pp < 2; ++pp) {
            int idx = t + pp * 256;          // 0..511
            int r   = idx & 63;
            int k4  = (idx >> 6) * 4;        // 0,4,...,28
            float4 w = *(const float4*)&W[r * 256 + kk + k4];
            Ws[(k4 + 0) * 64 + r] = w.x;
            Ws[(k4 + 1) * 64 + r] = w.y;
            Ws[(k4 + 2) * 64 + r] = w.z;
            Ws[(k4 + 3) * 64 + r] = w.w;
        }
        // Xs[k][col] = X[kk+k][col0+col]  (coalesced float4)
        #pragma unroll
        for (int pp = 0; pp < 4; ++pp) {
            int idx  = t + pp * 256;         // 0..1023 float4 slots
            int k    = idx >> 5;             // 0..31
            int c4   = (idx & 31) * 4;       // 0..124
            *(float4*)&Xs[k * 128 + c4] =
                *(const float4*)&Xb[(size_t)(kk + k) * HWN + col0 + c4];
        }
        __syncthreads();
        #pragma unroll 8
        for (int k = 0; k < 32; ++k) {
            float4 x  = *(const float4*)&Xs[k * 128 + tx * 4];
            float4 w0 = *(const float4*)&Ws[k * 64 + ty * 8];
            float4 w1 = *(const float4*)&Ws[k * 64 + ty * 8 + 4];
            float wr[8] = {w0.x, w0.y, w0.z, w0.w, w1.x, w1.y, w1.z, w1.w};
            float xc[4] = {x.x, x.y, x.z, x.w};
            #pragma unroll
            for (int i = 0; i < 8; ++i)
                #pragma unroll
                for (int j = 0; j < 4; ++j)
                    acc[i][j] += wr[i] * xc[j];
        }
        __syncthreads();
    }

    if (p < 3) {
        float* out = (p == 0 ? g_q : (p == 1 ? g_kl : g_kf)) + (size_t)b * C4 * HWN;
        #pragma unroll
        for (int i = 0; i < 8; ++i) {
            int r = ty * 8 + i;
            float bb = bias[r];
            float4 v = make_float4(acc[i][0] + bb, acc[i][1] + bb,
                                   acc[i][2] + bb, acc[i][3] + bb);
            *(float4*)&out[(size_t)r * HWN + col0 + tx * 4] = v;
        }
    } else {
        // v transposed: g_v[b][hw][c]
        #pragma unroll
        for (int i = 0; i < 8; ++i) {
            int r = ty * 8 + i;
            float bb = bias[r];
            #pragma unroll
            for (int j = 0; j < 4; ++j)
                g_v[((size_t)b * HWN + col0 + tx * 4 + j) * C4 + r] = acc[i][j] + bb;
        }
    }
}

// ---------------------------------------------------------------------------
// Kernel 2: fused flash attention (both sides). grid (64 qtiles, B, 2 sides).
// Per CTA: 64 queries x full 4096 keys in 64-key tiles, online softmax.
// 256 threads: ty=t/16 -> q rows ty*4..+3 ; tx=t%16 -> (S: keys tx*4..+3,
// O: channels tx*4..+3). 16-lane row groups == half warps -> shfl reductions.
// ---------------------------------------------------------------------------
__global__ __launch_bounds__(256) void attn_kernel()
{
    __shared__ float Qs [64 * 64];   // Qs[c][q]
    __shared__ float KPs[64 * 64];   // K tile [c][k], reused as P tile [q][k]
    __shared__ float Vt [64 * 64];   // Vt[k][c]

    const int qt   = blockIdx.x;     // 0..63
    const int b    = blockIdx.y;
    const int side = blockIdx.z;

    const float* Qg = g_q + (size_t)b * C4 * HWN;
    const float* Kg = (side == 0 ? g_kl : g_kf) + (size_t)b * C4 * HWN;
    const float* Vg = g_v + (size_t)b * HWN * C4;

    const int q0 = qt * 64;
    const int t  = threadIdx.x;
    const int ty = t >> 4;           // 0..15
    const int tx = t & 15;           // 0..15

    #pragma unroll
    for (int pp = 0; pp < 4; ++pp) {
        int idx = t + pp * 256;      // float4 slots
        int c   = idx >> 4;
        int q4  = (idx & 15) * 4;
        *(float4*)&Qs[c * 64 + q4] = *(const float4*)&Qg[(size_t)c * HWN + q0 + q4];
    }

    float m_run[4], l_run[4], o[4][4];
    #pragma unroll
    for (int i = 0; i < 4; ++i) {
        m_run[i] = -INFINITY; l_run[i] = 0.f;
        #pragma unroll
        for (int j = 0; j < 4; ++j) o[i][j] = 0.f;
    }

    for (int k0 = 0; k0 < HWN; k0 += 64) {
        __syncthreads();   // protect KPs/Vt from previous iteration readers (covers Q load on iter 0)
        #pragma unroll
        for (int pp = 0; pp < 4; ++pp) {
            int idx = t + pp * 256;
            int c   = idx >> 4;
            int k4  = (idx & 15) * 4;
            *(float4*)&KPs[c * 64 + k4] = *(const float4*)&Kg[(size_t)c * HWN + k0 + k4];
        }
        #pragma unroll
        for (int pp = 0; pp < 4; ++pp) {
            int idx = t + pp * 256;
            int kk  = idx >> 4;
            int c4  = (idx & 15) * 4;
            *(float4*)&Vt[kk * 64 + c4] = *(const float4*)&Vg[(size_t)(k0 + kk) * C4 + c4];
        }
        __syncthreads();

        // GEMM1: S[q][k] = sum_c Q[c][q] * K[c][k]
        float s[4][4];
        #pragma unroll
        for (int i = 0; i < 4; ++i)
            #pragma unroll
            for (int j = 0; j < 4; ++j) s[i][j] = 0.f;

        #pragma unroll 8
        for (int c = 0; c < 64; ++c) {
            float4 qv = *(const float4*)&Qs [c * 64 + ty * 4];
            float4 kv = *(const float4*)&KPs[c * 64 + tx * 4];
            float qa[4] = {qv.x, qv.y, qv.z, qv.w};
            float ka[4] = {kv.x, kv.y, kv.z, kv.w};
            #pragma unroll
            for (int i = 0; i < 4; ++i)
                #pragma unroll
                for (int j = 0; j < 4; ++j)
                    s[i][j] += qa[i] * ka[j];
        }

        // online softmax per q-row (reduce across 16 lanes = half warp)
        float alpha[4];
        #pragma unroll
        for (int i = 0; i < 4; ++i) {
            float tm = fmaxf(fmaxf(s[i][0], s[i][1]), fmaxf(s[i][2], s[i][3]));
            #pragma unroll
            for (int off = 8; off > 0; off >>= 1)
                tm = fmaxf(tm, __shfl_xor_sync(0xffffffffu, tm, off));
            float nm = fmaxf(m_run[i], tm);
            alpha[i] = __expf(m_run[i] - nm);
            m_run[i] = nm;
            float rs = 0.f;
            #pragma unroll
            for (int j = 0; j < 4; ++j) { s[i][j] = __expf(s[i][j] - nm); rs += s[i][j]; }
            #pragma unroll
            for (int off = 8; off > 0; off >>= 1)
                rs += __shfl_xor_sync(0xffffffffu, rs, off);
            l_run[i] = l_run[i] * alpha[i] + rs;
            #pragma unroll
            for (int j = 0; j < 4; ++j) o[i][j] *= alpha[i];
        }

        __syncthreads();   // everyone done reading KPs as K
        #pragma unroll
        for (int i = 0; i < 4; ++i)
            *(float4*)&KPs[(ty * 4 + i) * 64 + tx * 4] =
                make_float4(s[i][0], s[i][1], s[i][2], s[i][3]);
        __syncthreads();

        // GEMM2: O[q][c] += sum_k P[q][k] * V[k][c]
        #pragma unroll 8
        for (int k = 0; k < 64; ++k) {
            float4 vv = *(const float4*)&Vt[k * 64 + tx * 4];
            float p0 = KPs[(ty * 4 + 0) * 64 + k];
            float p1 = KPs[(ty * 4 + 1) * 64 + k];
            float p2 = KPs[(ty * 4 + 2) * 64 + k];
            float p3 = KPs[(ty * 4 + 3) * 64 + k];
            float va[4] = {vv.x, vv.y, vv.z, vv.w};
            float pa[4] = {p0, p1, p2, p3};
            #pragma unroll
            for (int i = 0; i < 4; ++i)
                #pragma unroll
                for (int j = 0; j < 4; ++j)
                    o[i][j] += pa[i] * va[j];
        }
    }

    // epilogue: normalize, write g_fused[b][hw][cf]
    #pragma unroll
    for (int i = 0; i < 4; ++i) {
        float invl = 1.f / l_run[i];
        float4 r = make_float4(o[i][0] * invl, o[i][1] * invl,
                               o[i][2] * invl, o[i][3] * invl);
        *(float4*)&g_fused[((size_t)b * HWN + q0 + ty * 4 + i) * 128 + side * 64 + tx * 4] = r;
    }
}

// ---------------------------------------------------------------------------
// Kernel 3: fire conv + BN + residual + ReLU.
// fired = Wfire[256,128] @ fused[128,4096]; out = relu(cur + fired*inv + shift)
// grid (32 hw-tiles, 4 row-tiles, B), block 256. Tile 64 rows x 128 cols, K=128.
// ---------------------------------------------------------------------------
__global__ __launch_bounds__(256) void fire_kernel(
    const float* __restrict__ cur,
    const float* __restrict__ Wfire, const float* __restrict__ bfire,
    const float* __restrict__ gamma, const float* __restrict__ beta,
    const float* __restrict__ mean,  const float* __restrict__ var,
    float* __restrict__ out)
{
    __shared__ float Ws[32 * 64];     // Ws[k][r]
    __shared__ float Xs[32 * 132];    // Xs[k][col], pitch 132 (float4-readable)

    const int tile = blockIdx.x;      // 0..31
    const int rt   = blockIdx.y;      // 0..3
    const int b    = blockIdx.z;
    const int r0   = rt * 64;
    const int col0 = tile * 128;
    const int t  = threadIdx.x;
    const int ty = t >> 5;
    const int tx = t & 31;

    const float* Fb = g_fused + (size_t)b * HWN * 128;

    float acc[8][4];
    #pragma unroll
    for (int i = 0; i < 8; ++i)
        #pragma unroll
        for (int j = 0; j < 4; ++j) acc[i][j] = 0.f;

    for (int kk = 0; kk < 128; kk += 32) {
        #pragma unroll
        for (int pp = 0; pp < 2; ++pp) {
            int idx = t + pp * 256;
            int r   = idx & 63;
            int k4  = (idx >> 6) * 4;
            float4 w = *(const float4*)&Wfire[(r0 + r) * 128 + kk + k4];
            Ws[(k4 + 0) * 64 + r] = w.x;
            Ws[(k4 + 1) * 64 + r] = w.y;
            Ws[(k4 + 2) * 64 + r] = w.z;
            Ws[(k4 + 3) * 64 + r] = w.w;
        }
        // transpose-load fused[hw-major] into Xs[k][col]
        #pragma unroll
        for (int pp = 0; pp < 4; ++pp) {
            int idx = t + pp * 256;          // 0..1023
            int col = idx >> 3;              // 0..127
            int k4  = (idx & 7) * 4;         // 0..28
            float4 x = *(const float4*)&Fb[(size_t)(col0 + col) * 128 + kk + k4];
            Xs[(k4 + 0) * 132 + col] = x.x;
            Xs[(k4 + 1) * 132 + col] = x.y;
            Xs[(k4 + 2) * 132 + col] = x.z;
            Xs[(k4 + 3) * 132 + col] = x.w;
        }
        __syncthreads();
        #pragma unroll 8
        for (int k = 0; k < 32; ++k) {
            float4 x  = *(const float4*)&Xs[k * 132 + tx * 4];
            float4 w0 = *(const float4*)&Ws[k * 64 + ty * 8];
            float4 w1 = *(const float4*)&Ws[k * 64 + ty * 8 + 4];
            float wr[8] = {w0.x, w0.y, w0.z, w0.w, w1.x, w1.y, w1.z, w1.w};
            float xc[4] = {x.x, x.y, x.z, x.w};
            #pragma unroll
            for (int i = 0; i < 8; ++i)
                #pragma unroll
                for (int j = 0; j < 4; ++j)
                    acc[i][j] += wr[i] * xc[j];
        }
        __syncthreads();
    }

    const float* curb = cur + (size_t)b * CC * HWN;
    #pragma unroll
    for (int i = 0; i < 8; ++i) {
        int r = r0 + ty * 8 + i;
        float inv   = gamma[r] * rsqrtf(var[r] + 1e-5f);
        float shift = beta[r] - mean[r] * inv;
        float bb    = bfire[r];
        size_t base = (size_t)r * HWN + col0 + tx * 4;
        float4 c4 = *(const float4*)&curb[base];
        float4 rv;
        rv.x = fmaxf(c4.x + (acc[i][0] + bb) * inv + shift, 0.f);
        rv.y = fmaxf(c4.y + (acc[i][1] + bb) * inv + shift, 0.f);
        rv.z = fmaxf(c4.z + (acc[i][2] + bb) * inv + shift, 0.f);
        rv.w = fmaxf(c4.w + (acc[i][3] + bb) * inv + shift, 0.f);
        *(float4*)&out[(size_t)b * CC * HWN + base] = rv;
    }
}

// ---------------------------------------------------------------------------
extern "C" void kernel_launch(void* const* d_in, const int* in_sizes, int n_in,
                              void* d_out, int out_size)
{
    const float* last  = (const float*)d_in[0];
    const float* cur   = (const float*)d_in[1];
    const float* fut   = (const float*)d_in[2];
    const float* Wqk   = (const float*)d_in[3];
    const float* bqk   = (const float*)d_in[4];
    const float* Wkl   = (const float*)d_in[5];
    const float* bkl   = (const float*)d_in[6];
    const float* Wkf   = (const float*)d_in[7];
    const float* bkf   = (const float*)d_in[8];
    const float* Wv    = (const float*)d_in[9];
    const float* bv    = (const float*)d_in[10];
    const float* Wfire = (const float*)d_in[11];
    const float* bfire = (const float*)d_in[12];
    const float* gamma = (const float*)d_in[13];
    const float* beta  = (const float*)d_in[14];
    const float* mean  = (const float*)d_in[15];
    const float* var   = (const float*)d_in[16];

    proj_kernel<<<dim3(32, BB, 4), 256>>>(last, cur, fut,
                                          Wqk, bqk, Wkl, bkl, Wkf, bkf, Wv, bv);
    attn_kernel<<<dim3(64, BB, 2), 256>>>();
    fire_kernel<<<dim3(32, 4, BB), 256>>>(cur, Wfire, bfire,
                                          gamma, beta, mean, var, (float*)d_out);
}

// round 12
// speedup vs baseline: 2.4690x; 2.3339x over previous
#include <cuda_runtime.h>
#include <cuda_bf16.h>
#include <cstdint>
#include <math.h>

#define BB   4
#define CC   256
#define C4   64
#define HWN  4096

// ---------------- scratch ----------------
__device__ __nv_bfloat16 g_qhi[BB * HWN * C4];       // [b][hw][c]
__device__ __nv_bfloat16 g_qlo[BB * HWN * C4];
__device__ __nv_bfloat16 g_khi[2 * BB * HWN * C4];   // [side][b][hw][c]
__device__ __nv_bfloat16 g_klo[2 * BB * HWN * C4];
__device__ __nv_bfloat16 g_vhi[BB * C4 * HWN];       // [b][c][hw]
__device__ __nv_bfloat16 g_vlo[BB * C4 * HWN];
__device__ float g_fused[BB * HWN * 128];            // [b][hw][cf]

#define SW128(x) ((x) ^ (((x) >> 3) & 0x70))

__device__ __forceinline__ uint32_t smem_to_u32(const void* p) {
    uint32_t a;
    asm("{ .reg .u64 t; cvta.to.shared.u64 t, %1; cvt.u32.u64 %0, t; }" : "=r"(a) : "l"(p));
    return a;
}
__device__ __forceinline__ uint32_t bf16pack2(float a, float b) {
    return (uint32_t)__bfloat16_as_ushort(__float2bfloat16_rn(a)) |
           ((uint32_t)__bfloat16_as_ushort(__float2bfloat16_rn(b)) << 16);
}
__device__ __forceinline__ void ldsm4(uint32_t r[4], uint32_t addr) {
    asm volatile("ldmatrix.sync.aligned.m8n8.x4.shared.b16 {%0,%1,%2,%3}, [%4];"
        : "=r"(r[0]), "=r"(r[1]), "=r"(r[2]), "=r"(r[3]) : "r"(addr));
}
__device__ __forceinline__ void mma16816(float* d, const uint32_t* a, const uint32_t* b) {
    asm volatile("mma.sync.aligned.m16n8k16.row.col.f32.bf16.bf16.f32 "
        "{%0,%1,%2,%3}, {%4,%5,%6,%7}, {%8,%9}, {%0,%1,%2,%3};"
        : "+f"(d[0]), "+f"(d[1]), "+f"(d[2]), "+f"(d[3])
        : "r"(a[0]), "r"(a[1]), "r"(a[2]), "r"(a[3]), "r"(b[0]), "r"(b[1]));
}

// ---------------------------------------------------------------------------
// Kernel 1: projections -> bf16 hi/lo. grid(32,B,4), block 256.
// Tile 64 c-rows x 128 hw-cols. Threads: 4 c x 8 hw.
// ---------------------------------------------------------------------------
__global__ __launch_bounds__(256) void proj_kernel(
    const float* __restrict__ last, const float* __restrict__ cur, const float* __restrict__ fut,
    const float* __restrict__ Wqk, const float* __restrict__ bqk,
    const float* __restrict__ Wkl, const float* __restrict__ bkl,
    const float* __restrict__ Wkf, const float* __restrict__ bkf,
    const float* __restrict__ Wv,  const float* __restrict__ bv)
{
    __shared__ float Ws[32 * 64];
    __shared__ float Xs[32 * 128];

    const int tile = blockIdx.x, b = blockIdx.y, p = blockIdx.z;
    const float *X, *W, *bias;
    if      (p == 0) { X = cur;  W = Wqk; bias = bqk; }
    else if (p == 1) { X = last; W = Wkl; bias = bkl; }
    else if (p == 2) { X = fut;  W = Wkf; bias = bkf; }
    else             { X = cur;  W = Wv;  bias = bv;  }

    const float* Xb = X + (size_t)b * CC * HWN;
    const int col0 = tile * 128;
    const int t    = threadIdx.x;
    const int r0   = (t & 15) * 4;
    const int colt = (t >> 4) * 8;

    float acc[4][8];
    #pragma unroll
    for (int i = 0; i < 4; ++i)
        #pragma unroll
        for (int j = 0; j < 8; ++j) acc[i][j] = 0.f;

    for (int kk = 0; kk < CC; kk += 32) {
        #pragma unroll
        for (int pp = 0; pp < 2; ++pp) {
            int idx = t + pp * 256, r = idx & 63, k4 = (idx >> 6) * 4;
            float4 w = *(const float4*)&W[r * 256 + kk + k4];
            Ws[(k4+0)*64+r] = w.x; Ws[(k4+1)*64+r] = w.y;
            Ws[(k4+2)*64+r] = w.z; Ws[(k4+3)*64+r] = w.w;
        }
        #pragma unroll
        for (int pp = 0; pp < 4; ++pp) {
            int idx = t + pp * 256, k = idx >> 5, c4 = (idx & 31) * 4;
            *(float4*)&Xs[k * 128 + c4] =
                *(const float4*)&Xb[(size_t)(kk + k) * HWN + col0 + c4];
        }
        __syncthreads();
        #pragma unroll 8
        for (int k = 0; k < 32; ++k) {
            float4 wv = *(const float4*)&Ws[k * 64 + r0];
            float4 x0 = *(const float4*)&Xs[k * 128 + colt];
            float4 x1 = *(const float4*)&Xs[k * 128 + colt + 4];
            float wr[4] = {wv.x, wv.y, wv.z, wv.w};
            float xc[8] = {x0.x, x0.y, x0.z, x0.w, x1.x, x1.y, x1.z, x1.w};
            #pragma unroll
            for (int i = 0; i < 4; ++i)
                #pragma unroll
                for (int j = 0; j < 8; ++j)
                    acc[i][j] += wr[i] * xc[j];
        }
        __syncthreads();
    }

    float b4[4];
    #pragma unroll
    for (int i = 0; i < 4; ++i) b4[i] = bias[r0 + i];

    if (p < 3) {
        __nv_bfloat16 *oh, *ol;
        if (p == 0)      { oh = g_qhi + (size_t)b * HWN * C4;        ol = g_qlo + (size_t)b * HWN * C4; }
        else if (p == 1) { oh = g_khi + (size_t)b * HWN * C4;        ol = g_klo + (size_t)b * HWN * C4; }
        else             { oh = g_khi + (size_t)(BB + b) * HWN * C4; ol = g_klo + (size_t)(BB + b) * HWN * C4; }
        #pragma unroll
        for (int j = 0; j < 8; ++j) {
            int hw = col0 + colt + j;
            float v[4], lo[4];
            #pragma unroll
            for (int i = 0; i < 4; ++i) {
                v[i]  = acc[i][j] + b4[i];
                lo[i] = v[i] - __bfloat162float(__float2bfloat16_rn(v[i]));
            }
            *(uint2*)(oh + (size_t)hw * C4 + r0) = make_uint2(bf16pack2(v[0],v[1]),  bf16pack2(v[2],v[3]));
            *(uint2*)(ol + (size_t)hw * C4 + r0) = make_uint2(bf16pack2(lo[0],lo[1]),bf16pack2(lo[2],lo[3]));
        }
    } else {
        __nv_bfloat16* vh = g_vhi + (size_t)b * C4 * HWN;
        __nv_bfloat16* vl = g_vlo + (size_t)b * C4 * HWN;
        #pragma unroll
        for (int i = 0; i < 4; ++i) {
            int r = r0 + i;
            float v[8], lo[8];
            #pragma unroll
            for (int j = 0; j < 8; ++j) {
                v[j]  = acc[i][j] + b4[i];
                lo[j] = v[j] - __bfloat162float(__float2bfloat16_rn(v[j]));
            }
            *(uint4*)(vh + (size_t)r * HWN + col0 + colt) =
                make_uint4(bf16pack2(v[0],v[1]), bf16pack2(v[2],v[3]), bf16pack2(v[4],v[5]), bf16pack2(v[6],v[7]));
            *(uint4*)(vl + (size_t)r * HWN + col0 + colt) =
                make_uint4(bf16pack2(lo[0],lo[1]),bf16pack2(lo[2],lo[3]),bf16pack2(lo[4],lo[5]),bf16pack2(lo[6],lo[7]));
        }
    }
}

// ---------------------------------------------------------------------------
// Kernel 2: mma.sync bf16 flash attention, no-max softmax.
// grid(64, B, 2), block 128 (4 warps). Warp = 16 q-rows x 64 keys/tile.
// 3-term bf16 split on both QK^T and P.V. O accumulates in regs all 64 iters.
// ---------------------------------------------------------------------------
__global__ __launch_bounds__(128, 3) void attn_kernel()
{
    // smem: QHI | QLO | KHI | KLO | VHI | VLO, each 64 rows x 128B, SW128
    __shared__ __align__(1024) uint8_t smem[6 * 8192];
    const uint32_t u_base = smem_to_u32(smem);
    const uint32_t u_qhi = u_base,          u_qlo = u_base + 8192;
    const uint32_t u_khi = u_base + 16384,  u_klo = u_base + 24576;
    const uint32_t u_vhi = u_base + 32768,  u_vlo = u_base + 40960;

    const int qt = blockIdx.x, b = blockIdx.y, side = blockIdx.z;
    const int q0c = qt * 64;
    const int t = threadIdx.x, w = t >> 5, lane = t & 31;
    const int g = lane >> 3, r = lane & 7;

    const uint8_t* gq_hi = (const uint8_t*)(g_qhi + (size_t)b * HWN * C4);
    const uint8_t* gq_lo = (const uint8_t*)(g_qlo + (size_t)b * HWN * C4);
    const uint8_t* gk_hi = (const uint8_t*)(g_khi + (size_t)(side * BB + b) * HWN * C4);
    const uint8_t* gk_lo = (const uint8_t*)(g_klo + (size_t)(side * BB + b) * HWN * C4);
    const uint8_t* gv_hi = (const uint8_t*)(g_vhi + (size_t)b * C4 * HWN);
    const uint8_t* gv_lo = (const uint8_t*)(g_vlo + (size_t)b * C4 * HWN);

    // ---- Q tile (64 x 64 bf16, hi+lo) -> smem ----
    #pragma unroll
    for (int pp = 0; pp < 4; ++pp) {
        int idx = t + pp * 128;          // 0..511 uint4 slots
        int row = idx >> 3, cb = (idx & 7) * 16;
        uint32_t sw = SW128((uint32_t)(row * 128 + cb));
        size_t go = ((size_t)(q0c + row) * C4) * 2 + cb;
        *(uint4*)(smem + 0    + sw) = *(const uint4*)(gq_hi + go);
        *(uint4*)(smem + 8192 + sw) = *(const uint4*)(gq_lo + go);
    }
    __syncthreads();

    // ---- Q fragments (A, m16k16): rows 16w..16w+15, 4 k-steps ----
    uint32_t qhi[4][4], qlo[4][4];
    #pragma unroll
    for (int s = 0; s < 4; ++s) {
        uint32_t off = SW128((uint32_t)((16 * w + (g & 1) * 8 + r) * 128 + (g >> 1) * 16 + 32 * s));
        ldsm4(qhi[s], u_qhi + off);
        ldsm4(qlo[s], u_qlo + off);
    }

    float O[8][4];
    #pragma unroll
    for (int i = 0; i < 8; ++i)
        #pragma unroll
        for (int j = 0; j < 4; ++j) O[i][j] = 0.f;
    float lsum0 = 0.f, lsum1 = 0.f;

    for (int k0 = 0; k0 < HWN; k0 += 64) {
        // ---- K [key][c] and V [c][key] tiles -> smem (hi+lo) ----
        #pragma unroll
        for (int pp = 0; pp < 4; ++pp) {
            int idx = t + pp * 128;
            int row = idx >> 3, cb = (idx & 7) * 16;
            uint32_t sw = SW128((uint32_t)(row * 128 + cb));
            size_t gko = ((size_t)(k0 + row) * C4) * 2 + cb;
            *(uint4*)(smem + 16384 + sw) = *(const uint4*)(gk_hi + gko);
            *(uint4*)(smem + 24576 + sw) = *(const uint4*)(gk_lo + gko);
            size_t gvo = ((size_t)row * HWN + k0) * 2 + cb;
            *(uint4*)(smem + 32768 + sw) = *(const uint4*)(gv_hi + gvo);
            *(uint4*)(smem + 40960 + sw) = *(const uint4*)(gv_lo + gvo);
        }
        __syncthreads();

        // ---- GEMM1: S[16q x 64k] = Qhi.Khi + Qhi.Klo + Qlo.Khi ----
        float S[8][4];
        #pragma unroll
        for (int i = 0; i < 8; ++i)
            #pragma unroll
            for (int j = 0; j < 4; ++j) S[i][j] = 0.f;

        #pragma unroll
        for (int s = 0; s < 4; ++s) {
            #pragma unroll
            for (int jp = 0; jp < 4; ++jp) {
                uint32_t koff = SW128((uint32_t)((jp * 16 + (g >> 1) * 8 + r) * 128 + (g & 1) * 16 + 32 * s));
                uint32_t kh[4], kl[4];
                ldsm4(kh, u_khi + koff);
                ldsm4(kl, u_klo + koff);
                mma16816(S[2*jp],   qhi[s], kh + 0);
                mma16816(S[2*jp+1], qhi[s], kh + 2);
                mma16816(S[2*jp],   qhi[s], kl + 0);
                mma16816(S[2*jp+1], qhi[s], kl + 2);
                mma16816(S[2*jp],   qlo[s], kh + 0);
                mma16816(S[2*jp+1], qlo[s], kh + 2);
            }
        }

        // ---- exp (no max subtraction), row-sum accum, P hi/lo repack ----
        uint32_t phi[4][4], plo[4][4];
        #pragma unroll
        for (int jt = 0; jt < 8; ++jt) {
            float e0 = __expf(S[jt][0]), e1 = __expf(S[jt][1]);
            float e2 = __expf(S[jt][2]), e3 = __expf(S[jt][3]);
            lsum0 += e0 + e1;
            lsum1 += e2 + e3;
            __nv_bfloat16 h0 = __float2bfloat16_rn(e0), h1 = __float2bfloat16_rn(e1);
            __nv_bfloat16 h2 = __float2bfloat16_rn(e2), h3 = __float2bfloat16_rn(e3);
            int ks = jt >> 1, sl = (jt & 1) * 2;
            phi[ks][sl]     = (uint32_t)__bfloat16_as_ushort(h0) | ((uint32_t)__bfloat16_as_ushort(h1) << 16);
            phi[ks][sl + 1] = (uint32_t)__bfloat16_as_ushort(h2) | ((uint32_t)__bfloat16_as_ushort(h3) << 16);
            plo[ks][sl]     = bf16pack2(e0 - __bfloat162float(h0), e1 - __bfloat162float(h1));
            plo[ks][sl + 1] = bf16pack2(e2 - __bfloat162float(h2), e3 - __bfloat162float(h3));
        }

        // ---- GEMM2: O[16q x 64c] += Phi.Vhi + Phi.Vlo + Plo.Vhi ----
        #pragma unroll
        for (int tp = 0; tp < 4; ++tp) {
            #pragma unroll
            for (int j = 0; j < 4; ++j) {
                uint32_t voff = SW128((uint32_t)((tp * 16 + (g >> 1) * 8 + r) * 128 + (g & 1) * 16 + 32 * j));
                uint32_t vh[4], vl[4];
                ldsm4(vh, u_vhi + voff);
                ldsm4(vl, u_vlo + voff);
                mma16816(O[2*tp],   phi[j], vh + 0);
                mma16816(O[2*tp+1], phi[j], vh + 2);
                mma16816(O[2*tp],   phi[j], vl + 0);
                mma16816(O[2*tp+1], phi[j], vl + 2);
                mma16816(O[2*tp],   plo[j], vh + 0);
                mma16816(O[2*tp+1], plo[j], vh + 2);
            }
        }
        __syncthreads();
    }

    // ---- normalize and write g_fused ----
    lsum0 += __shfl_xor_sync(0xffffffffu, lsum0, 1);
    lsum0 += __shfl_xor_sync(0xffffffffu, lsum0, 2);
    lsum1 += __shfl_xor_sync(0xffffffffu, lsum1, 1);
    lsum1 += __shfl_xor_sync(0xffffffffu, lsum1, 2);
    const float i0 = 1.0f / lsum0, i1 = 1.0f / lsum1;

    const int qr0 = q0c + 16 * w + (lane >> 2);
    const int qr1 = qr0 + 8;
    float* fb = g_fused + (size_t)b * HWN * 128 + side * 64;
    #pragma unroll
    for (int tt = 0; tt < 8; ++tt) {
        int ct = 8 * tt + 2 * (lane & 3);
        *(float2*)&fb[(size_t)qr0 * 128 + ct] = make_float2(O[tt][0] * i0, O[tt][1] * i0);
        *(float2*)&fb[(size_t)qr1 * 128 + ct] = make_float2(O[tt][2] * i1, O[tt][3] * i1);
    }
}

// ---------------------------------------------------------------------------
// Kernel 3: fire conv + BN + residual + ReLU (unchanged).
// ---------------------------------------------------------------------------
__global__ __launch_bounds__(256) void fire_kernel(
    const float* __restrict__ cur,
    const float* __restrict__ Wfire, const float* __restrict__ bfire,
    const float* __restrict__ gamma, const float* __restrict__ beta,
    const float* __restrict__ mean,  const float* __restrict__ var,
    float* __restrict__ out)
{
    __shared__ float Ws[32 * 64];
    __shared__ float Xs[32 * 132];

    const int tile = blockIdx.x, rt = blockIdx.y, b = blockIdx.z;
    const int r0 = rt * 64, col0 = tile * 128;
    const int t = threadIdx.x, ty = t >> 5, tx = t & 31;
    const float* Fb = g_fused + (size_t)b * HWN * 128;

    float acc[8][4];
    #pragma unroll
    for (int i = 0; i < 8; ++i)
        #pragma unroll
        for (int j = 0; j < 4; ++j) acc[i][j] = 0.f;

    for (int kk = 0; kk < 128; kk += 32) {
        #pragma unroll
        for (int pp = 0; pp < 2; ++pp) {
            int idx = t + pp * 256, r = idx & 63, k4 = (idx >> 6) * 4;
            float4 w = *(const float4*)&Wfire[(r0 + r) * 128 + kk + k4];
            Ws[(k4+0)*64+r] = w.x; Ws[(k4+1)*64+r] = w.y;
            Ws[(k4+2)*64+r] = w.z; Ws[(k4+3)*64+r] = w.w;
        }
        #pragma unroll
        for (int pp = 0; pp < 4; ++pp) {
            int idx = t + pp * 256, col = idx >> 3, k4 = (idx & 7) * 4;
            float4 x = *(const float4*)&Fb[(size_t)(col0 + col) * 128 + kk + k4];
            Xs[(k4+0)*132+col] = x.x; Xs[(k4+1)*132+col] = x.y;
            Xs[(k4+2)*132+col] = x.z; Xs[(k4+3)*132+col] = x.w;
        }
        __syncthreads();
        #pragma unroll 8
        for (int k = 0; k < 32; ++k) {
            float4 x  = *(const float4*)&Xs[k * 132 + tx * 4];
            float4 w0 = *(const float4*)&Ws[k * 64 + ty * 8];
            float4 w1 = *(const float4*)&Ws[k * 64 + ty * 8 + 4];
            float wr[8] = {w0.x, w0.y, w0.z, w0.w, w1.x, w1.y, w1.z, w1.w};
            float xc[4] = {x.x, x.y, x.z, x.w};
            #pragma unroll
            for (int i = 0; i < 8; ++i)
                #pragma unroll
                for (int j = 0; j < 4; ++j)
                    acc[i][j] += wr[i] * xc[j];
        }
        __syncthreads();
    }

    const float* curb = cur + (size_t)b * CC * HWN;
    #pragma unroll
    for (int i = 0; i < 8; ++i) {
        int r = r0 + ty * 8 + i;
        float inv   = gamma[r] * rsqrtf(var[r] + 1e-5f);
        float shift = beta[r] - mean[r] * inv;
        float bb    = bfire[r];
        size_t base = (size_t)r * HWN + col0 + tx * 4;
        float4 c4 = *(const float4*)&curb[base];
        float4 rv;
        rv.x = fmaxf(c4.x + (acc[i][0] + bb) * inv + shift, 0.f);
        rv.y = fmaxf(c4.y + (acc[i][1] + bb) * inv + shift, 0.f);
        rv.z = fmaxf(c4.z + (acc[i][2] + bb) * inv + shift, 0.f);
        rv.w = fmaxf(c4.w + (acc[i][3] + bb) * inv + shift, 0.f);
        *(float4*)&out[(size_t)b * CC * HWN + base] = rv;
    }
}

// ---------------------------------------------------------------------------
extern "C" void kernel_launch(void* const* d_in, const int* in_sizes, int n_in,
                              void* d_out, int out_size)
{
    const float* last  = (const float*)d_in[0];
    const float* cur   = (const float*)d_in[1];
    const float* fut   = (const float*)d_in[2];
    const float* Wqk   = (const float*)d_in[3];
    const float* bqk   = (const float*)d_in[4];
    const float* Wkl   = (const float*)d_in[5];
    const float* bkl   = (const float*)d_in[6];
    const float* Wkf   = (const float*)d_in[7];
    const float* bkf   = (const float*)d_in[8];
    const float* Wv    = (const float*)d_in[9];
    const float* bv    = (const float*)d_in[10];
    const float* Wfire = (const float*)d_in[11];
    const float* bfire = (const float*)d_in[12];
    const float* gamma = (const float*)d_in[13];
    const float* beta  = (const float*)d_in[14];
    const float* mean  = (const float*)d_in[15];
    const float* var   = (const float*)d_in[16];

    proj_kernel<<<dim3(32, BB, 4), 256>>>(last, cur, fut,
                                          Wqk, bqk, Wkl, bkl, Wkf, bkf, Wv, bv);
    attn_kernel<<<dim3(64, BB, 2), 128>>>();
    fire_kernel<<<dim3(32, 4, BB), 256>>>(cur, Wfire, bfire,
                                          gamma, beta, mean, var, (float*)d_out);
}

// round 14
// speedup vs baseline: 2.9868x; 1.2097x over previous
#include <cuda_runtime.h>
#include <cuda_bf16.h>
#include <cstdint>
#include <math.h>

#define BB   4
#define CC   256
#define C4   64
#define HWN  4096
#define QT   128

// ---------------- scratch ----------------
__device__ __nv_bfloat16 g_qhi[BB * HWN * C4];       // [b][hw][c]
__device__ __nv_bfloat16 g_qlo[BB * HWN * C4];
__device__ __nv_bfloat16 g_khi[2 * BB * HWN * C4];   // [side][b][hw][c]
__device__ __nv_bfloat16 g_klo[2 * BB * HWN * C4];
__device__ __nv_bfloat16 g_vhi[BB * C4 * HWN];       // [b][c][hw]
__device__ __nv_bfloat16 g_vlo[BB * C4 * HWN];
__device__ float g_fused[BB * HWN * 128];            // [b][hw][cf]

#define SW128(x) ((x) ^ (((x) >> 3) & 0x70))

__device__ __forceinline__ uint32_t smem_to_u32(const void* p) {
    uint32_t a;
    asm("{ .reg .u64 t; cvta.to.shared.u64 t, %1; cvt.u32.u64 %0, t; }" : "=r"(a) : "l"(p));
    return a;
}
__device__ __forceinline__ uint32_t bf16pack2(float a, float b) {
    return (uint32_t)__bfloat16_as_ushort(__float2bfloat16_rn(a)) |
           ((uint32_t)__bfloat16_as_ushort(__float2bfloat16_rn(b)) << 16);
}
__device__ __forceinline__ void ldsm4(uint32_t r[4], uint32_t addr) {
    asm volatile("ldmatrix.sync.aligned.m8n8.x4.shared.b16 {%0,%1,%2,%3}, [%4];"
        : "=r"(r[0]), "=r"(r[1]), "=r"(r[2]), "=r"(r[3]) : "r"(addr));
}
__device__ __forceinline__ void mma16816(float* d, const uint32_t* a, const uint32_t* b) {
    asm volatile("mma.sync.aligned.m16n8k16.row.col.f32.bf16.bf16.f32 "
        "{%0,%1,%2,%3}, {%4,%5,%6,%7}, {%8,%9}, {%0,%1,%2,%3};"
        : "+f"(d[0]), "+f"(d[1]), "+f"(d[2]), "+f"(d[3])
        : "r"(a[0]), "r"(a[1]), "r"(a[2]), "r"(a[3]), "r"(b[0]), "r"(b[1]));
}
__device__ __forceinline__ void cp_async16(uint32_t dst, const void* src) {
    asm volatile("cp.async.cg.shared.global [%0], [%1], 16;" :: "r"(dst), "l"(src) : "memory");
}

// ---------------------------------------------------------------------------
// Kernel 1: projections -> bf16 hi/lo. grid(32,B,4), block 256.
// ---------------------------------------------------------------------------
__global__ __launch_bounds__(256) void proj_kernel(
    const float* __restrict__ last, const float* __restrict__ cur, const float* __restrict__ fut,
    const float* __restrict__ Wqk, const float* __restrict__ bqk,
    const float* __restrict__ Wkl, const float* __restrict__ bkl,
    const float* __restrict__ Wkf, const float* __restrict__ bkf,
    const float* __restrict__ Wv,  const float* __restrict__ bv)
{
    __shared__ float Ws[32 * 64];
    __shared__ float Xs[32 * 128];

    const int tile = blockIdx.x, b = blockIdx.y, p = blockIdx.z;
    const float *X, *W, *bias;
    if      (p == 0) { X = cur;  W = Wqk; bias = bqk; }
    else if (p == 1) { X = last; W = Wkl; bias = bkl; }
    else if (p == 2) { X = fut;  W = Wkf; bias = bkf; }
    else             { X = cur;  W = Wv;  bias = bv;  }

    const float* Xb = X + (size_t)b * CC * HWN;
    const int col0 = tile * 128;
    const int t    = threadIdx.x;
    const int r0   = (t & 15) * 4;
    const int colt = (t >> 4) * 8;

    float acc[4][8];
    #pragma unroll
    for (int i = 0; i < 4; ++i)
        #pragma unroll
        for (int j = 0; j < 8; ++j) acc[i][j] = 0.f;

    for (int kk = 0; kk < CC; kk += 32) {
        #pragma unroll
        for (int pp = 0; pp < 2; ++pp) {
            int idx = t + pp * 256, r = idx & 63, k4 = (idx >> 6) * 4;
            float4 w = *(const float4*)&W[r * 256 + kk + k4];
            Ws[(k4+0)*64+r] = w.x; Ws[(k4+1)*64+r] = w.y;
            Ws[(k4+2)*64+r] = w.z; Ws[(k4+3)*64+r] = w.w;
        }
        #pragma unroll
        for (int pp = 0; pp < 4; ++pp) {
            int idx = t + pp * 256, k = idx >> 5, c4 = (idx & 31) * 4;
            *(float4*)&Xs[k * 128 + c4] =
                *(const float4*)&Xb[(size_t)(kk + k) * HWN + col0 + c4];
        }
        __syncthreads();
        #pragma unroll 8
        for (int k = 0; k < 32; ++k) {
            float4 wv = *(const float4*)&Ws[k * 64 + r0];
            float4 x0 = *(const float4*)&Xs[k * 128 + colt];
            float4 x1 = *(const float4*)&Xs[k * 128 + colt + 4];
            float wr[4] = {wv.x, wv.y, wv.z, wv.w};
            float xc[8] = {x0.x, x0.y, x0.z, x0.w, x1.x, x1.y, x1.z, x1.w};
            #pragma unroll
            for (int i = 0; i < 4; ++i)
                #pragma unroll
                for (int j = 0; j < 8; ++j)
                    acc[i][j] += wr[i] * xc[j];
        }
        __syncthreads();
    }

    float b4[4];
    #pragma unroll
    for (int i = 0; i < 4; ++i) b4[i] = bias[r0 + i];

    if (p < 3) {
        __nv_bfloat16 *oh, *ol;
        if (p == 0)      { oh = g_qhi + (size_t)b * HWN * C4;        ol = g_qlo + (size_t)b * HWN * C4; }
        else if (p == 1) { oh = g_khi + (size_t)b * HWN * C4;        ol = g_klo + (size_t)b * HWN * C4; }
        else             { oh = g_khi + (size_t)(BB + b) * HWN * C4; ol = g_klo + (size_t)(BB + b) * HWN * C4; }
        #pragma unroll
        for (int j = 0; j < 8; ++j) {
            int hw = col0 + colt + j;
            float v[4], lo[4];
            #pragma unroll
            for (int i = 0; i < 4; ++i) {
                v[i]  = acc[i][j] + b4[i];
                lo[i] = v[i] - __bfloat162float(__float2bfloat16_rn(v[i]));
            }
            *(uint2*)(oh + (size_t)hw * C4 + r0) = make_uint2(bf16pack2(v[0],v[1]),  bf16pack2(v[2],v[3]));
            *(uint2*)(ol + (size_t)hw * C4 + r0) = make_uint2(bf16pack2(lo[0],lo[1]),bf16pack2(lo[2],lo[3]));
        }
    } else {
        __nv_bfloat16* vh = g_vhi + (size_t)b * C4 * HWN;
        __nv_bfloat16* vl = g_vlo + (size_t)b * C4 * HWN;
        #pragma unroll
        for (int i = 0; i < 4; ++i) {
            int r = r0 + i;
            float v[8], lo[8];
            #pragma unroll
            for (int j = 0; j < 8; ++j) {
                v[j]  = acc[i][j] + b4[i];
                lo[j] = v[j] - __bfloat162float(__float2bfloat16_rn(v[j]));
            }
            *(uint4*)(vh + (size_t)r * HWN + col0 + colt) =
                make_uint4(bf16pack2(v[0],v[1]), bf16pack2(v[2],v[3]), bf16pack2(v[4],v[5]), bf16pack2(v[6],v[7]));
            *(uint4*)(vl + (size_t)r * HWN + col0 + colt) =
                make_uint4(bf16pack2(lo[0],lo[1]),bf16pack2(lo[2],lo[3]),bf16pack2(lo[4],lo[5]),bf16pack2(lo[6],lo[7]));
        }
    }
}

// ---------------------------------------------------------------------------
// Kernel 2: mma.sync bf16 flash attention, no-max softmax, cp.async
// double-buffered K/V. grid(32, B, 2), block 256 (8 warps x 16 q-rows).
// smem (dynamic 64KB): stage s at s*32768: KHI|KLO|VHI|VLO (8KB each).
// Q staging overlays stage 1 during prologue.
// ---------------------------------------------------------------------------
__global__ void __launch_bounds__(256, 2) attn_kernel()
{
    extern __shared__ __align__(1024) uint8_t smem[];
    const uint32_t u_base = smem_to_u32(smem);

    const int qt = blockIdx.x, b = blockIdx.y, side = blockIdx.z;
    const int q0c = qt * QT;
    const int t = threadIdx.x, w = t >> 5, lane = t & 31;
    const int g = lane >> 3, r = lane & 7;

    const uint8_t* gq_hi = (const uint8_t*)(g_qhi + (size_t)b * HWN * C4);
    const uint8_t* gq_lo = (const uint8_t*)(g_qlo + (size_t)b * HWN * C4);
    const uint8_t* gk_hi = (const uint8_t*)(g_khi + (size_t)(side * BB + b) * HWN * C4);
    const uint8_t* gk_lo = (const uint8_t*)(g_klo + (size_t)(side * BB + b) * HWN * C4);
    const uint8_t* gv_hi = (const uint8_t*)(g_vhi + (size_t)b * C4 * HWN);
    const uint8_t* gv_lo = (const uint8_t*)(g_vlo + (size_t)b * C4 * HWN);

    // issue one 32KB K/V tile into a stage via cp.async (8 x 16B per thread)
    auto issue_tile = [&](int it, uint32_t stage) {
        const int k0 = it * 64;
        #pragma unroll
        for (int pp = 0; pp < 8; ++pp) {
            int idx = t + pp * 256;          // 0..2047
            int arr = idx >> 9;              // 0:KHI 1:KLO 2:VHI 3:VLO
            int sl  = idx & 511;
            int row = sl >> 3, cb = (sl & 7) * 16;
            uint32_t dst = stage + (uint32_t)arr * 8192 + SW128((uint32_t)(row * 128 + cb));
            const uint8_t* src;
            if (arr == 0)      src = gk_hi + ((size_t)(k0 + row) * C4) * 2 + cb;
            else if (arr == 1) src = gk_lo + ((size_t)(k0 + row) * C4) * 2 + cb;
            else if (arr == 2) src = gv_hi + ((size_t)row * HWN + k0) * 2 + cb;
            else               src = gv_lo + ((size_t)row * HWN + k0) * 2 + cb;
            cp_async16(dst, src);
        }
        asm volatile("cp.async.commit_group;" ::: "memory");
    };

    // ---- prologue: tile0 in flight while Q stages through stage-1 area ----
    issue_tile(0, u_base);

    #pragma unroll
    for (int pp = 0; pp < 4; ++pp) {
        int idx = t + pp * 256;              // 0..1023 (128 rows x 8 slots)
        int row = idx >> 3, cb = (idx & 7) * 16;
        uint32_t sw = SW128((uint32_t)(row * 128 + cb));
        size_t go = ((size_t)(q0c + row) * C4) * 2 + cb;
        *(uint4*)(smem + 32768 + sw) = *(const uint4*)(gq_hi + go);
        *(uint4*)(smem + 49152 + sw) = *(const uint4*)(gq_lo + go);
    }
    __syncthreads();

    uint32_t qhi[4][4], qlo[4][4];
    #pragma unroll
    for (int s = 0; s < 4; ++s) {
        uint32_t off = SW128((uint32_t)((16 * w + (g & 1) * 8 + r) * 128 + (g >> 1) * 16 + 32 * s));
        ldsm4(qhi[s], u_base + 32768 + off);
        ldsm4(qlo[s], u_base + 49152 + off);
    }
    __syncthreads();    // Q area free -> stage 1 usable

    float O[8][4];
    #pragma unroll
    for (int i = 0; i < 8; ++i)
        #pragma unroll
        for (int j = 0; j < 4; ++j) O[i][j] = 0.f;
    float lsum0 = 0.f, lsum1 = 0.f;

    for (int it = 0; it < 64; ++it) {
        const uint32_t stage = u_base + (uint32_t)(it & 1) * 32768;
        if (it < 63) {
            issue_tile(it + 1, u_base + (uint32_t)((it + 1) & 1) * 32768);
            asm volatile("cp.async.wait_group 1;" ::: "memory");
        } else {
            asm volatile("cp.async.wait_group 0;" ::: "memory");
        }
        __syncthreads();

        const uint32_t u_khi = stage, u_klo = stage + 8192;
        const uint32_t u_vhi = stage + 16384, u_vlo = stage + 24576;

        // ---- GEMM1: S[16q x 64k] = Qhi.Khi + Qhi.Klo + Qlo.Khi ----
        float S[8][4];
        #pragma unroll
        for (int i = 0; i < 8; ++i)
            #pragma unroll
            for (int j = 0; j < 4; ++j) S[i][j] = 0.f;

        #pragma unroll
        for (int s = 0; s < 4; ++s) {
            #pragma unroll
            for (int jp = 0; jp < 4; ++jp) {
                uint32_t koff = SW128((uint32_t)((jp * 16 + (g >> 1) * 8 + r) * 128 + (g & 1) * 16 + 32 * s));
                uint32_t kh[4], kl[4];
                ldsm4(kh, u_khi + koff);
                ldsm4(kl, u_klo + koff);
                mma16816(S[2*jp],   qhi[s], kh + 0);
                mma16816(S[2*jp+1], qhi[s], kh + 2);
                mma16816(S[2*jp],   qhi[s], kl + 0);
                mma16816(S[2*jp+1], qhi[s], kl + 2);
                mma16816(S[2*jp],   qlo[s], kh + 0);
                mma16816(S[2*jp+1], qlo[s], kh + 2);
            }
        }

        // ---- exp (no max), row-sum accum, P hi/lo repack ----
        uint32_t phi[4][4], plo[4][4];
        #pragma unroll
        for (int jt = 0; jt < 8; ++jt) {
            float e0 = __expf(S[jt][0]), e1 = __expf(S[jt][1]);
            float e2 = __expf(S[jt][2]), e3 = __expf(S[jt][3]);
            lsum0 += e0 + e1;
            lsum1 += e2 + e3;
            __nv_bfloat16 h0 = __float2bfloat16_rn(e0), h1 = __float2bfloat16_rn(e1);
            __nv_bfloat16 h2 = __float2bfloat16_rn(e2), h3 = __float2bfloat16_rn(e3);
            int ks = jt >> 1, sl = (jt & 1) * 2;
            phi[ks][sl]     = (uint32_t)__bfloat16_as_ushort(h0) | ((uint32_t)__bfloat16_as_ushort(h1) << 16);
            phi[ks][sl + 1] = (uint32_t)__bfloat16_as_ushort(h2) | ((uint32_t)__bfloat16_as_ushort(h3) << 16);
            plo[ks][sl]     = bf16pack2(e0 - __bfloat162float(h0), e1 - __bfloat162float(h1));
            plo[ks][sl + 1] = bf16pack2(e2 - __bfloat162float(h2), e3 - __bfloat162float(h3));
        }

        // ---- GEMM2: O[16q x 64c] += Phi.Vhi + Phi.Vlo + Plo.Vhi ----
        #pragma unroll
        for (int tp = 0; tp < 4; ++tp) {
            #pragma unroll
            for (int j = 0; j < 4; ++j) {
                uint32_t voff = SW128((uint32_t)((tp * 16 + (g >> 1) * 8 + r) * 128 + (g & 1) * 16 + 32 * j));
                uint32_t vh[4], vl[4];
                ldsm4(vh, u_vhi + voff);
                ldsm4(vl, u_vlo + voff);
                mma16816(O[2*tp],   phi[j], vh + 0);
                mma16816(O[2*tp+1], phi[j], vh + 2);
                mma16816(O[2*tp],   phi[j], vl + 0);
                mma16816(O[2*tp+1], phi[j], vl + 2);
                mma16816(O[2*tp],   plo[j], vh + 0);
                mma16816(O[2*tp+1], plo[j], vh + 2);
            }
        }
        __syncthreads();   // all warps done reading this stage
    }

    // ---- normalize and write g_fused ----
    lsum0 += __shfl_xor_sync(0xffffffffu, lsum0, 1);
    lsum0 += __shfl_xor_sync(0xffffffffu, lsum0, 2);
    lsum1 += __shfl_xor_sync(0xffffffffu, lsum1, 1);
    lsum1 += __shfl_xor_sync(0xffffffffu, lsum1, 2);
    const float i0 = 1.0f / lsum0, i1 = 1.0f / lsum1;

    const int qr0 = q0c + 16 * w + (lane >> 2);
    const int qr1 = qr0 + 8;
    float* fb = g_fused + (size_t)b * HWN * 128 + side * 64;
    #pragma unroll
    for (int tt = 0; tt < 8; ++tt) {
        int ct = 8 * tt + 2 * (lane & 3);
        *(float2*)&fb[(size_t)qr0 * 128 + ct] = make_float2(O[tt][0] * i0, O[tt][1] * i0);
        *(float2*)&fb[(size_t)qr1 * 128 + ct] = make_float2(O[tt][2] * i1, O[tt][3] * i1);
    }
}

// ---------------------------------------------------------------------------
// Kernel 3: fire conv + BN + residual + ReLU (unchanged).
// ---------------------------------------------------------------------------
__global__ __launch_bounds__(256) void fire_kernel(
    const float* __restrict__ cur,
    const float* __restrict__ Wfire, const float* __restrict__ bfire,
    const float* __restrict__ gamma, const float* __restrict__ beta,
    const float* __restrict__ mean,  const float* __restrict__ var,
    float* __restrict__ out)
{
    __shared__ float Ws[32 * 64];
    __shared__ float Xs[32 * 132];

    const int tile = blockIdx.x, rt = blockIdx.y, b = blockIdx.z;
    const int r0 = rt * 64, col0 = tile * 128;
    const int t = threadIdx.x, ty = t >> 5, tx = t & 31;
    const float* Fb = g_fused + (size_t)b * HWN * 128;

    float acc[8][4];
    #pragma unroll
    for (int i = 0; i < 8; ++i)
        #pragma unroll
        for (int j = 0; j < 4; ++j) acc[i][j] = 0.f;

    for (int kk = 0; kk < 128; kk += 32) {
        #pragma unroll
        for (int pp = 0; pp < 2; ++pp) {
            int idx = t + pp * 256, r = idx & 63, k4 = (idx >> 6) * 4;
            float4 w = *(const float4*)&Wfire[(r0 + r) * 128 + kk + k4];
            Ws[(k4+0)*64+r] = w.x; Ws[(k4+1)*64+r] = w.y;
            Ws[(k4+2)*64+r] = w.z; Ws[(k4+3)*64+r] = w.w;
        }
        #pragma unroll
        for (int pp = 0; pp < 4; ++pp) {
            int idx = t + pp * 256, col = idx >> 3, k4 = (idx & 7) * 4;
            float4 x = *(const float4*)&Fb[(size_t)(col0 + col) * 128 + kk + k4];
            Xs[(k4+0)*132+col] = x.x; Xs[(k4+1)*132+col] = x.y;
            Xs[(k4+2)*132+col] = x.z; Xs[(k4+3)*132+col] = x.w;
        }
        __syncthreads();
        #pragma unroll 8
        for (int k = 0; k < 32; ++k) {
            float4 x  = *(const float4*)&Xs[k * 132 + tx * 4];
            float4 w0 = *(const float4*)&Ws[k * 64 + ty * 8];
            float4 w1 = *(const float4*)&Ws[k * 64 + ty * 8 + 4];
            float wr[8] = {w0.x, w0.y, w0.z, w0.w, w1.x, w1.y, w1.z, w1.w};
            float xc[4] = {x.x, x.y, x.z, x.w};
            #pragma unroll
            for (int i = 0; i < 8; ++i)
                #pragma unroll
                for (int j = 0; j < 4; ++j)
                    acc[i][j] += wr[i] * xc[j];
        }
        __syncthreads();
    }

    const float* curb = cur + (size_t)b * CC * HWN;
    #pragma unroll
    for (int i = 0; i < 8; ++i) {
        int r = r0 + ty * 8 + i;
        float inv   = gamma[r] * rsqrtf(var[r] + 1e-5f);
        float shift = beta[r] - mean[r] * inv;
        float bb    = bfire[r];
        size_t base = (size_t)r * HWN + col0 + tx * 4;
        float4 c4 = *(const float4*)&curb[base];
        float4 rv;
        rv.x = fmaxf(c4.x + (acc[i][0] + bb) * inv + shift, 0.f);
        rv.y = fmaxf(c4.y + (acc[i][1] + bb) * inv + shift, 0.f);
        rv.z = fmaxf(c4.z + (acc[i][2] + bb) * inv + shift, 0.f);
        rv.w = fmaxf(c4.w + (acc[i][3] + bb) * inv + shift, 0.f);
        *(float4*)&out[(size_t)b * CC * HWN + base] = rv;
    }
}

// ---------------------------------------------------------------------------
extern "C" void kernel_launch(void* const* d_in, const int* in_sizes, int n_in,
                              void* d_out, int out_size)
{
    const float* last  = (const float*)d_in[0];
    const float* cur   = (const float*)d_in[1];
    const float* fut   = (const float*)d_in[2];
    const float* Wqk   = (const float*)d_in[3];
    const float* bqk   = (const float*)d_in[4];
    const float* Wkl   = (const float*)d_in[5];
    const float* bkl   = (const float*)d_in[6];
    const float* Wkf   = (const float*)d_in[7];
    const float* bkf   = (const float*)d_in[8];
    const float* Wv    = (const float*)d_in[9];
    const float* bv    = (const float*)d_in[10];
    const float* Wfire = (const float*)d_in[11];
    const float* bfire = (const float*)d_in[12];
    const float* gamma = (const float*)d_in[13];
    const float* beta  = (const float*)d_in[14];
    const float* mean  = (const float*)d_in[15];
    const float* var   = (const float*)d_in[16];

    cudaFuncSetAttribute(attn_kernel, cudaFuncAttributeMaxDynamicSharedMemorySize, 65536);

    proj_kernel<<<dim3(32, BB, 4), 256>>>(last, cur, fut,
                                          Wqk, bqk, Wkl, bkl, Wkf, bkf, Wv, bv);
    attn_kernel<<<dim3(32, BB, 2), 256, 65536>>>();
    fire_kernel<<<dim3(32, 4, BB), 256>>>(cur, Wfire, bfire,
                                          gamma, beta, mean, var, (float*)d_out);
}

// round 16
// speedup vs baseline: 3.3974x; 1.1375x over previous
#include <cuda_runtime.h>
#include <cuda_bf16.h>
#include <cstdint>
#include <math.h>

#define BB   4
#define CC   256
#define C4   64
#define HWN  4096
#define QT   128

// ---------------- scratch ----------------
__device__ __nv_bfloat16 g_qhi[BB * HWN * C4];       // [b][hw][c]   (q pre-scaled by log2e)
__device__ __nv_bfloat16 g_qlo[BB * HWN * C4];
__device__ __nv_bfloat16 g_khi[2 * BB * HWN * C4];   // [side][b][hw][c]
__device__ __nv_bfloat16 g_klo[2 * BB * HWN * C4];
__device__ __nv_bfloat16 g_vhi[BB * HWN * C4];       // [b][hw][c]   (NEW: same layout as k)
__device__ __nv_bfloat16 g_vlo[BB * HWN * C4];
__device__ __nv_bfloat16 g_fhi[BB * HWN * 128];      // fused [b][hw][cf] bf16 hi
__device__ __nv_bfloat16 g_flo[BB * HWN * 128];      // fused lo
__device__ __nv_bfloat16 g_Wphi[4 * 64 * 256];       // proj weights [p][cout][cin] hi
__device__ __nv_bfloat16 g_Wplo[4 * 64 * 256];
__device__ __nv_bfloat16 g_Wfhi[256 * 128];          // fire weights [cout][cf] hi
__device__ __nv_bfloat16 g_Wflo[256 * 128];

#define SW128(x) ((x) ^ (((x) >> 3) & 0x70))
#define L2E 1.4426950408889634f

__device__ __forceinline__ uint32_t smem_to_u32(const void* p) {
    uint32_t a;
    asm("{ .reg .u64 t; cvta.to.shared.u64 t, %1; cvt.u32.u64 %0, t; }" : "=r"(a) : "l"(p));
    return a;
}
__device__ __forceinline__ uint32_t bf16pack2(float a, float b) {
    return (uint32_t)__bfloat16_as_ushort(__float2bfloat16_rn(a)) |
           ((uint32_t)__bfloat16_as_ushort(__float2bfloat16_rn(b)) << 16);
}
__device__ __forceinline__ void ldsm4(uint32_t r[4], uint32_t addr) {
    asm volatile("ldmatrix.sync.aligned.m8n8.x4.shared.b16 {%0,%1,%2,%3}, [%4];"
        : "=r"(r[0]), "=r"(r[1]), "=r"(r[2]), "=r"(r[3]) : "r"(addr));
}
__device__ __forceinline__ void ldsm4t(uint32_t r[4], uint32_t addr) {
    asm volatile("ldmatrix.sync.aligned.m8n8.x4.trans.shared.b16 {%0,%1,%2,%3}, [%4];"
        : "=r"(r[0]), "=r"(r[1]), "=r"(r[2]), "=r"(r[3]) : "r"(addr));
}
__device__ __forceinline__ void mma16816(float* d, const uint32_t* a, const uint32_t* b) {
    asm volatile("mma.sync.aligned.m16n8k16.row.col.f32.bf16.bf16.f32 "
        "{%0,%1,%2,%3}, {%4,%5,%6,%7}, {%8,%9}, {%0,%1,%2,%3};"
        : "+f"(d[0]), "+f"(d[1]), "+f"(d[2]), "+f"(d[3])
        : "r"(a[0]), "r"(a[1]), "r"(a[2]), "r"(a[3]), "r"(b[0]), "r"(b[1]));
}
__device__ __forceinline__ void cp_async16(uint32_t dst, const void* src) {
    asm volatile("cp.async.cg.shared.global [%0], [%1], 16;" :: "r"(dst), "l"(src) : "memory");
}
__device__ __forceinline__ float ex2(float x) {
    float y;
    asm("ex2.approx.f32 %0, %1;" : "=f"(y) : "f"(x));
    return y;
}
// split 8 fp32 -> 16B hi + 16B lo bf16
__device__ __forceinline__ void split8(float4 a, float4 b, uint4& hi, uint4& lo) {
    float v[8] = {a.x, a.y, a.z, a.w, b.x, b.y, b.z, b.w};
    uint32_t hp[4], lp[4];
    #pragma unroll
    for (int i = 0; i < 4; ++i) {
        __nv_bfloat16 h0 = __float2bfloat16_rn(v[2*i]);
        __nv_bfloat16 h1 = __float2bfloat16_rn(v[2*i+1]);
        hp[i] = (uint32_t)__bfloat16_as_ushort(h0) | ((uint32_t)__bfloat16_as_ushort(h1) << 16);
        lp[i] = bf16pack2(v[2*i] - __bfloat162float(h0), v[2*i+1] - __bfloat162float(h1));
    }
    hi = make_uint4(hp[0], hp[1], hp[2], hp[3]);
    lo = make_uint4(lp[0], lp[1], lp[2], lp[3]);
}

// ---------------------------------------------------------------------------
// Kernel 0: split all weights to bf16 hi/lo (q weights scaled by log2e).
// ---------------------------------------------------------------------------
__global__ __launch_bounds__(256) void wsplit_kernel(
    const float* __restrict__ Wqk, const float* __restrict__ Wkl,
    const float* __restrict__ Wkf, const float* __restrict__ Wv,
    const float* __restrict__ Wfire)
{
    int gid = blockIdx.x * 256 + threadIdx.x;
    float v;
    __nv_bfloat16 *dh, *dl;
    if (gid < 65536) {
        int p = gid >> 14, i = gid & 16383;
        const float* W = (p == 0) ? Wqk : (p == 1) ? Wkl : (p == 2) ? Wkf : Wv;
        v = W[i];
        if (p == 0) v *= L2E;
        dh = g_Wphi + gid; dl = g_Wplo + gid;
    } else {
        int i = gid - 65536;
        v = Wfire[i];
        dh = g_Wfhi + i; dl = g_Wflo + i;
    }
    __nv_bfloat16 h = __float2bfloat16_rn(v);
    *dh = h;
    *dl = __float2bfloat16_rn(v - __bfloat162float(h));
}

// ---------------------------------------------------------------------------
// Kernel 1: HMMA projections. grid(32 hw-tiles, B, 4 proj), block 256.
// C[m=hw 128][n=cout 64] = X^T * W^T, 3-term bf16 split, K=256 in 4 chunks.
// A = X^T via ldsm.trans from natural [c][hw] tiles; B = W rows non-trans.
// smem 48KB: Xa_hi@0 Xa_lo@8K Xb_hi@16K Xb_lo@24K (two 64-hw halves), Wh@32K Wl@40K.
// Output [hw][c] bf16 hi/lo.
// ---------------------------------------------------------------------------
__global__ __launch_bounds__(256) void proj_kernel(
    const float* __restrict__ last, const float* __restrict__ cur, const float* __restrict__ fut,
    const float* __restrict__ bqk, const float* __restrict__ bkl,
    const float* __restrict__ bkf, const float* __restrict__ bv)
{
    __shared__ __align__(1024) uint8_t sm[49152];
    const uint32_t u = smem_to_u32(sm);

    const int tile = blockIdx.x, b = blockIdx.y, p = blockIdx.z;
    const float* X    = (p == 1) ? last : (p == 2) ? fut : cur;
    const float* bias = (p == 0) ? bqk : (p == 1) ? bkl : (p == 2) ? bkf : bv;
    const __nv_bfloat16* Wh = g_Wphi + p * 16384;
    const __nv_bfloat16* Wl = g_Wplo + p * 16384;
    const float* Xb = X + (size_t)b * CC * HWN + tile * 128;

    const int t = threadIdx.x, w = t >> 5, lane = t & 31;
    const int g = lane >> 3, r = lane & 7;

    float C[8][4];
    #pragma unroll
    for (int i = 0; i < 8; ++i)
        #pragma unroll
        for (int j = 0; j < 4; ++j) C[i][j] = 0.f;

    const uint32_t xbase = u + ((w & 4) ? 16384u : 0u);
    const uint32_t mloc  = (uint32_t)(w & 3) * 32u;

    for (int kc = 0; kc < 4; ++kc) {
        __syncthreads();
        // W chunk [64 cout][64 cin] hi/lo, SW128
        #pragma unroll
        for (int pp = 0; pp < 2; ++pp) {
            int idx = t + pp * 256;          // 0..511
            int row = idx >> 3, c16 = idx & 7;
            uint32_t dst = SW128((uint32_t)(row * 128 + c16 * 16));
            *(uint4*)(sm + 32768 + dst) = *(const uint4*)((const uint8_t*)(Wh + row * 256 + kc * 64) + c16 * 16);
            *(uint4*)(sm + 40960 + dst) = *(const uint4*)((const uint8_t*)(Wl + row * 256 + kc * 64) + c16 * 16);
        }
        // X chunk [64 c][128 hw] fp32 -> bf16 hi/lo halves
        #pragma unroll
        for (int pp = 0; pp < 4; ++pp) {
            int idx = t + pp * 256;          // 0..1023
            int row = idx >> 4, col8 = (idx & 15) * 8;
            const float* src = Xb + (size_t)(kc * 64 + row) * HWN + col8;
            float4 u0 = *(const float4*)src;
            float4 u1 = *(const float4*)(src + 4);
            uint4 hi, lo;
            split8(u0, u1, hi, lo);
            int half = col8 >> 6;
            uint32_t off = SW128((uint32_t)(row * 128 + (col8 & 63) * 2));
            *(uint4*)(sm + half * 16384 + off)        = hi;
            *(uint4*)(sm + half * 16384 + 8192 + off) = lo;
        }
        __syncthreads();

        #pragma unroll
        for (int s = 0; s < 4; ++s) {
            uint32_t aoff = SW128((uint32_t)((16 * s + (g >> 1) * 8 + r) * 128) + mloc + (uint32_t)(g & 1) * 16);
            uint32_t ah[4], al[4];
            ldsm4t(ah, xbase + aoff);
            ldsm4t(al, xbase + 8192 + aoff);
            #pragma unroll
            for (int jp = 0; jp < 4; ++jp) {
                uint32_t boff = SW128((uint32_t)((16 * jp + (g >> 1) * 8 + r) * 128 + (g & 1) * 16 + 32 * s));
                uint32_t bh[4], bl[4];
                ldsm4(bh, u + 32768 + boff);
                ldsm4(bl, u + 40960 + boff);
                mma16816(C[2*jp],   ah, bh + 0);
                mma16816(C[2*jp+1], ah, bh + 2);
                mma16816(C[2*jp],   ah, bl + 0);
                mma16816(C[2*jp+1], ah, bl + 2);
                mma16816(C[2*jp],   al, bh + 0);
                mma16816(C[2*jp+1], al, bh + 2);
            }
        }
    }

    // epilogue: +bias, split hi/lo, write [hw][c]
    __nv_bfloat16 *oh, *ol;
    if (p == 0)      { oh = g_qhi + (size_t)b * HWN * C4;        ol = g_qlo + (size_t)b * HWN * C4; }
    else if (p == 1) { oh = g_khi + (size_t)b * HWN * C4;        ol = g_klo + (size_t)b * HWN * C4; }
    else if (p == 2) { oh = g_khi + (size_t)(BB + b) * HWN * C4; ol = g_klo + (size_t)(BB + b) * HWN * C4; }
    else             { oh = g_vhi + (size_t)b * HWN * C4;        ol = g_vlo + (size_t)b * HWN * C4; }

    const float bscale = (p == 0) ? L2E : 1.0f;
    const int hw0 = tile * 128 + w * 16 + (lane >> 2);
    #pragma unroll
    for (int j = 0; j < 8; ++j) {
        int n = 8 * j + 2 * (lane & 3);
        float b0 = bias[n] * bscale, b1 = bias[n + 1] * bscale;
        float v0 = C[j][0] + b0, v1 = C[j][1] + b1;
        float v2 = C[j][2] + b0, v3 = C[j][3] + b1;
        __nv_bfloat16 h0 = __float2bfloat16_rn(v0), h1 = __float2bfloat16_rn(v1);
        __nv_bfloat16 h2 = __float2bfloat16_rn(v2), h3 = __float2bfloat16_rn(v3);
        *(uint32_t*)(oh + (size_t)hw0 * C4 + n) =
            (uint32_t)__bfloat16_as_ushort(h0) | ((uint32_t)__bfloat16_as_ushort(h1) << 16);
        *(uint32_t*)(oh + (size_t)(hw0 + 8) * C4 + n) =
            (uint32_t)__bfloat16_as_ushort(h2) | ((uint32_t)__bfloat16_as_ushort(h3) << 16);
        *(uint32_t*)(ol + (size_t)hw0 * C4 + n) =
            bf16pack2(v0 - __bfloat162float(h0), v1 - __bfloat162float(h1));
        *(uint32_t*)(ol + (size_t)(hw0 + 8) * C4 + n) =
            bf16pack2(v2 - __bfloat162float(h2), v3 - __bfloat162float(h3));
    }
}

// ---------------------------------------------------------------------------
// Kernel 2: mma.sync bf16 flash attention (no-max softmax, exp2 domain),
// cp.async double-buffered K/V. grid(32, B, 2), block 256.
// V now [hw][c] like K; GEMM2 B-frags via ldmatrix.trans.
// ---------------------------------------------------------------------------
__global__ void __launch_bounds__(256, 2) attn_kernel()
{
    extern __shared__ __align__(1024) uint8_t smem[];
    const uint32_t u_base = smem_to_u32(smem);

    const int qt = blockIdx.x, b = blockIdx.y, side = blockIdx.z;
    const int q0c = qt * QT;
    const int t = threadIdx.x, w = t >> 5, lane = t & 31;
    const int g = lane >> 3, r = lane & 7;

    const uint8_t* gq_hi = (const uint8_t*)(g_qhi + (size_t)b * HWN * C4);
    const uint8_t* gq_lo = (const uint8_t*)(g_qlo + (size_t)b * HWN * C4);
    const uint8_t* gk_hi = (const uint8_t*)(g_khi + (size_t)(side * BB + b) * HWN * C4);
    const uint8_t* gk_lo = (const uint8_t*)(g_klo + (size_t)(side * BB + b) * HWN * C4);
    const uint8_t* gv_hi = (const uint8_t*)(g_vhi + (size_t)b * HWN * C4);
    const uint8_t* gv_lo = (const uint8_t*)(g_vlo + (size_t)b * HWN * C4);

    auto issue_tile = [&](int it, uint32_t stage) {
        const int k0 = it * 64;
        #pragma unroll
        for (int pp = 0; pp < 8; ++pp) {
            int idx = t + pp * 256;          // 0..2047
            int arr = idx >> 9;              // 0:KHI 1:KLO 2:VHI 3:VLO
            int sl  = idx & 511;
            int row = sl >> 3, cb = (sl & 7) * 16;
            uint32_t dst = stage + (uint32_t)arr * 8192 + SW128((uint32_t)(row * 128 + cb));
            size_t go = ((size_t)(k0 + row) * C4) * 2 + cb;
            const uint8_t* src;
            if (arr == 0)      src = gk_hi + go;
            else if (arr == 1) src = gk_lo + go;
            else if (arr == 2) src = gv_hi + go;
            else               src = gv_lo + go;
            cp_async16(dst, src);
        }
        asm volatile("cp.async.commit_group;" ::: "memory");
    };

    issue_tile(0, u_base);

    #pragma unroll
    for (int pp = 0; pp < 4; ++pp) {
        int idx = t + pp * 256;
        int row = idx >> 3, cb = (idx & 7) * 16;
        uint32_t sw = SW128((uint32_t)(row * 128 + cb));
        size_t go = ((size_t)(q0c + row) * C4) * 2 + cb;
        *(uint4*)(smem + 32768 + sw) = *(const uint4*)(gq_hi + go);
        *(uint4*)(smem + 49152 + sw) = *(const uint4*)(gq_lo + go);
    }
    __syncthreads();

    uint32_t qhi[4][4], qlo[4][4];
    #pragma unroll
    for (int s = 0; s < 4; ++s) {
        uint32_t off = SW128((uint32_t)((16 * w + (g & 1) * 8 + r) * 128 + (g >> 1) * 16 + 32 * s));
        ldsm4(qhi[s], u_base + 32768 + off);
        ldsm4(qlo[s], u_base + 49152 + off);
    }
    __syncthreads();

    float O[8][4];
    #pragma unroll
    for (int i = 0; i < 8; ++i)
        #pragma unroll
        for (int j = 0; j < 4; ++j) O[i][j] = 0.f;
    float lsum0 = 0.f, lsum1 = 0.f;

    for (int it = 0; it < 64; ++it) {
        const uint32_t stage = u_base + (uint32_t)(it & 1) * 32768;
        if (it < 63) {
            issue_tile(it + 1, u_base + (uint32_t)((it + 1) & 1) * 32768);
            asm volatile("cp.async.wait_group 1;" ::: "memory");
        } else {
            asm volatile("cp.async.wait_group 0;" ::: "memory");
        }
        __syncthreads();

        const uint32_t u_khi = stage, u_klo = stage + 8192;
        const uint32_t u_vhi = stage + 16384, u_vlo = stage + 24576;

        // GEMM1: S = Qhi.Khi + Qhi.Klo + Qlo.Khi
        float S[8][4];
        #pragma unroll
        for (int i = 0; i < 8; ++i)
            #pragma unroll
            for (int j = 0; j < 4; ++j) S[i][j] = 0.f;

        #pragma unroll
        for (int s = 0; s < 4; ++s) {
            #pragma unroll
            for (int jp = 0; jp < 4; ++jp) {
                uint32_t koff = SW128((uint32_t)((jp * 16 + (g >> 1) * 8 + r) * 128 + (g & 1) * 16 + 32 * s));
                uint32_t kh[4], kl[4];
                ldsm4(kh, u_khi + koff);
                ldsm4(kl, u_klo + koff);
                mma16816(S[2*jp],   qhi[s], kh + 0);
                mma16816(S[2*jp+1], qhi[s], kh + 2);
                mma16816(S[2*jp],   qhi[s], kl + 0);
                mma16816(S[2*jp+1], qhi[s], kl + 2);
                mma16816(S[2*jp],   qlo[s], kh + 0);
                mma16816(S[2*jp+1], qlo[s], kh + 2);
            }
        }

        // exp2 (q pre-scaled by log2e), row sums, P hi/lo repack
        uint32_t phi[4][4], plo[4][4];
        #pragma unroll
        for (int jt = 0; jt < 8; ++jt) {
            float e0 = ex2(S[jt][0]), e1 = ex2(S[jt][1]);
            float e2 = ex2(S[jt][2]), e3 = ex2(S[jt][3]);
            lsum0 += e0 + e1;
            lsum1 += e2 + e3;
            __nv_bfloat16 h0 = __float2bfloat16_rn(e0), h1 = __float2bfloat16_rn(e1);
            __nv_bfloat16 h2 = __float2bfloat16_rn(e2), h3 = __float2bfloat16_rn(e3);
            int ks = jt >> 1, sl = (jt & 1) * 2;
            phi[ks][sl]     = (uint32_t)__bfloat16_as_ushort(h0) | ((uint32_t)__bfloat16_as_ushort(h1) << 16);
            phi[ks][sl + 1] = (uint32_t)__bfloat16_as_ushort(h2) | ((uint32_t)__bfloat16_as_ushort(h3) << 16);
            plo[ks][sl]     = bf16pack2(e0 - __bfloat162float(h0), e1 - __bfloat162float(h1));
            plo[ks][sl + 1] = bf16pack2(e2 - __bfloat162float(h2), e3 - __bfloat162float(h3));
        }

        // GEMM2: O += Phi.Vhi + Phi.Vlo + Plo.Vhi  (V [key][c], trans B-frags)
        #pragma unroll
        for (int tp = 0; tp < 4; ++tp) {
            #pragma unroll
            for (int j = 0; j < 4; ++j) {
                uint32_t voff = SW128((uint32_t)((16 * tp + (g & 1) * 8 + r) * 128 + 32 * j + (g >> 1) * 16));
                uint32_t vh[4], vl[4];
                ldsm4t(vh, u_vhi + voff);
                ldsm4t(vl, u_vlo + voff);
                mma16816(O[2*j],   phi[tp], vh + 0);
                mma16816(O[2*j+1], phi[tp], vh + 2);
                mma16816(O[2*j],   phi[tp], vl + 0);
                mma16816(O[2*j+1], phi[tp], vl + 2);
                mma16816(O[2*j],   plo[tp], vh + 0);
                mma16816(O[2*j+1], plo[tp], vh + 2);
            }
        }
        __syncthreads();
    }

    // normalize, split hi/lo, write fused bf16
    lsum0 += __shfl_xor_sync(0xffffffffu, lsum0, 1);
    lsum0 += __shfl_xor_sync(0xffffffffu, lsum0, 2);
    lsum1 += __shfl_xor_sync(0xffffffffu, lsum1, 1);
    lsum1 += __shfl_xor_sync(0xffffffffu, lsum1, 2);
    const float i0 = 1.0f / lsum0, i1 = 1.0f / lsum1;

    const int qr0 = q0c + 16 * w + (lane >> 2);
    const int qr1 = qr0 + 8;
    __nv_bfloat16* fh = g_fhi + (size_t)b * HWN * 128 + side * 64;
    __nv_bfloat16* fl = g_flo + (size_t)b * HWN * 128 + side * 64;
    #pragma unroll
    for (int tt = 0; tt < 8; ++tt) {
        int ct = 8 * tt + 2 * (lane & 3);
        float v0 = O[tt][0] * i0, v1 = O[tt][1] * i0;
        float v2 = O[tt][2] * i1, v3 = O[tt][3] * i1;
        __nv_bfloat16 h0 = __float2bfloat16_rn(v0), h1 = __float2bfloat16_rn(v1);
        __nv_bfloat16 h2 = __float2bfloat16_rn(v2), h3 = __float2bfloat16_rn(v3);
        *(uint32_t*)(fh + (size_t)qr0 * 128 + ct) =
            (uint32_t)__bfloat16_as_ushort(h0) | ((uint32_t)__bfloat16_as_ushort(h1) << 16);
        *(uint32_t*)(fh + (size_t)qr1 * 128 + ct) =
            (uint32_t)__bfloat16_as_ushort(h2) | ((uint32_t)__bfloat16_as_ushort(h3) << 16);
        *(uint32_t*)(fl + (size_t)qr0 * 128 + ct) =
            bf16pack2(v0 - __bfloat162float(h0), v1 - __bfloat162float(h1));
        *(uint32_t*)(fl + (size_t)qr1 * 128 + ct) =
            bf16pack2(v2 - __bfloat162float(h2), v3 - __bfloat162float(h3));
    }
}

// ---------------------------------------------------------------------------
// Kernel 3: HMMA fire conv + BN + residual + ReLU. grid(32, 4, B), block 256.
// C[m=cout 64][n=hw 128] = Wfire * fused, K=128, 3-term split.
// smem 96KB dyn: W0h@0 W0l@8K W1h@16K W1l@24K; F0h@32K F0l@48K F1h@64K F1l@80K.
// ---------------------------------------------------------------------------
__global__ void __launch_bounds__(256, 2) fire_kernel(
    const float* __restrict__ cur,
    const float* __restrict__ bfire,
    const float* __restrict__ gamma, const float* __restrict__ beta,
    const float* __restrict__ mean,  const float* __restrict__ var,
    float* __restrict__ out)
{
    extern __shared__ __align__(1024) uint8_t smem[];
    const uint32_t u = smem_to_u32(smem);

    const int tile = blockIdx.x, rt = blockIdx.y, b = blockIdx.z;
    const int r0 = rt * 64, col0 = tile * 128;
    const int t = threadIdx.x, w = t >> 5, lane = t & 31;
    const int g = lane >> 3, r = lane & 7;

    // W: [64 cout][128 cf] hi/lo, split into two 64-cf halves
    #pragma unroll
    for (int pp = 0; pp < 8; ++pp) {
        int idx = t + pp * 256;              // 0..2047
        int arr = idx >> 9;                  // 0:W0h 1:W0l 2:W1h 3:W1l
        int sl  = idx & 511;
        int row = sl >> 3, c16 = sl & 7;
        int khalf = arr >> 1;
        const __nv_bfloat16* src = ((arr & 1) ? g_Wflo : g_Wfhi) + (size_t)(r0 + row) * 128 + khalf * 64 + c16 * 8;
        cp_async16(u + (uint32_t)arr * 8192 + SW128((uint32_t)(row * 128 + c16 * 16)), src);
    }
    // F: fused [128 hw][128 cf] hi/lo, two cf-halves
    #pragma unroll
    for (int pp = 0; pp < 16; ++pp) {
        int idx = t + pp * 256;              // 0..4095
        int arr = idx >> 10;                 // 0:F0h 1:F0l 2:F1h 3:F1l
        int sl  = idx & 1023;
        int row = sl >> 3, c16 = sl & 7;
        int khalf = arr >> 1;
        const __nv_bfloat16* src = ((arr & 1) ? g_flo : g_fhi) +
            (size_t)b * HWN * 128 + (size_t)(col0 + row) * 128 + khalf * 64 + c16 * 8;
        cp_async16(u + 32768 + (uint32_t)arr * 16384 + SW128((uint32_t)(row * 128 + c16 * 16)), src);
    }
    asm volatile("cp.async.commit_group;" ::: "memory");
    asm volatile("cp.async.wait_group 0;" ::: "memory");
    __syncthreads();

    float C[8][4];
    #pragma unroll
    for (int i = 0; i < 8; ++i)
        #pragma unroll
        for (int j = 0; j < 4; ++j) C[i][j] = 0.f;

    const int nwbase = (w >> 2) * 64;        // warp hw-half
    #pragma unroll
    for (int s8 = 0; s8 < 8; ++s8) {
        int kh = s8 >> 2, s = s8 & 3;
        uint32_t wbase = u + (uint32_t)kh * 16384;
        uint32_t fbase = u + 32768 + (uint32_t)kh * 32768;
        uint32_t aoff = SW128((uint32_t)(((w & 3) * 16 + (g & 1) * 8 + r) * 128 + (g >> 1) * 16 + 32 * s));
        uint32_t ah[4], al[4];
        ldsm4(ah, wbase + aoff);
        ldsm4(al, wbase + 8192 + aoff);
        #pragma unroll
        for (int nf = 0; nf < 4; ++nf) {
            uint32_t boff = SW128((uint32_t)((nwbase + 16 * nf + (g >> 1) * 8 + r) * 128 + (g & 1) * 16 + 32 * s));
            uint32_t bh[4], bl[4];
            ldsm4(bh, fbase + boff);
            ldsm4(bl, fbase + 16384 + boff);
            mma16816(C[2*nf],   ah, bh + 0);
            mma16816(C[2*nf+1], ah, bh + 2);
            mma16816(C[2*nf],   ah, bl + 0);
            mma16816(C[2*nf+1], ah, bl + 2);
            mma16816(C[2*nf],   al, bh + 0);
            mma16816(C[2*nf+1], al, bh + 2);
        }
    }

    // epilogue: bias + BN + residual + relu, write fp32 [c][hw]
    const int m0 = r0 + (w & 3) * 16 + (lane >> 2);
    const int m1 = m0 + 8;
    const float inv0 = gamma[m0] * rsqrtf(var[m0] + 1e-5f);
    const float sh0  = beta[m0] - mean[m0] * inv0;
    const float bb0  = bfire[m0];
    const float inv1 = gamma[m1] * rsqrtf(var[m1] + 1e-5f);
    const float sh1  = beta[m1] - mean[m1] * inv1;
    const float bb1  = bfire[m1];

    const float* curb = cur + (size_t)b * CC * HWN;
    float* outb = out + (size_t)b * CC * HWN;
    const int hwb = col0 + nwbase;
    #pragma unroll
    for (int j = 0; j < 8; ++j) {
        int n = hwb + 8 * j + 2 * (lane & 3);
        float2 c0 = *(const float2*)&curb[(size_t)m0 * HWN + n];
        float2 c1 = *(const float2*)&curb[(size_t)m1 * HWN + n];
        float2 o0, o1;
        o0.x = fmaxf(c0.x + (C[j][0] + bb0) * inv0 + sh0, 0.f);
        o0.y = fmaxf(c0.y + (C[j][1] + bb0) * inv0 + sh0, 0.f);
        o1.x = fmaxf(c1.x + (C[j][2] + bb1) * inv1 + sh1, 0.f);
        o1.y = fmaxf(c1.y + (C[j][3] + bb1) * inv1 + sh1, 0.f);
        *(float2*)&outb[(size_t)m0 * HWN + n] = o0;
        *(float2*)&outb[(size_t)m1 * HWN + n] = o1;
    }
}

// ---------------------------------------------------------------------------
extern "C" void kernel_launch(void* const* d_in, const int* in_sizes, int n_in,
                              void* d_out, int out_size)
{
    const float* last  = (const float*)d_in[0];
    const float* cur   = (const float*)d_in[1];
    const float* fut   = (const float*)d_in[2];
    const float* Wqk   = (const float*)d_in[3];
    const float* bqk   = (const float*)d_in[4];
    const float* Wkl   = (const float*)d_in[5];
    const float* bkl   = (const float*)d_in[6];
    const float* Wkf   = (const float*)d_in[7];
    const float* bkf   = (const float*)d_in[8];
    const float* Wv    = (const float*)d_in[9];
    const float* bv    = (const float*)d_in[10];
    const float* Wfire = (const float*)d_in[11];
    const float* bfire = (const float*)d_in[12];
    const float* gamma = (const float*)d_in[13];
    const float* beta  = (const float*)d_in[14];
    const float* mean  = (const float*)d_in[15];
    const float* var   = (const float*)d_in[16];

    cudaFuncSetAttribute(attn_kernel, cudaFuncAttributeMaxDynamicSharedMemorySize, 65536);
    cudaFuncSetAttribute(fire_kernel, cudaFuncAttributeMaxDynamicSharedMemorySize, 98304);

    wsplit_kernel<<<384, 256>>>(Wqk, Wkl, Wkf, Wv, Wfire);
    proj_kernel<<<dim3(32, BB, 4), 256>>>(last, cur, fut, bqk, bkl, bkf, bv);
    attn_kernel<<<dim3(32, BB, 2), 256, 65536>>>();
    fire_kernel<<<dim3(32, 4, BB), 256, 98304>>>(cur, bfire, gamma, beta, mean, var, (float*)d_out);
}

// round 17
// speedup vs baseline: 3.4724x; 1.0221x over previous
#include <cuda_runtime.h>
#include <cuda_bf16.h>
#include <cstdint>
#include <math.h>

#define BB   4
#define CC   256
#define C4   64
#define HWN  4096
#define QT   128

// ---------------- scratch ----------------
__device__ __nv_bfloat16 g_qhi[BB * HWN * C4];       // [b][hw][c]   (q pre-scaled by log2e)
__device__ __nv_bfloat16 g_qlo[BB * HWN * C4];
__device__ __nv_bfloat16 g_khi[2 * BB * HWN * C4];   // [side][b][hw][c]
__device__ __nv_bfloat16 g_klo[2 * BB * HWN * C4];
__device__ __nv_bfloat16 g_vhi[BB * HWN * C4];       // [b][hw][c]
__device__ __nv_bfloat16 g_vlo[BB * HWN * C4];
__device__ __nv_bfloat16 g_fhi[BB * HWN * 128];      // fused [b][hw][cf] bf16 hi
__device__ __nv_bfloat16 g_flo[BB * HWN * 128];      // fused lo
__device__ __nv_bfloat16 g_Wphi[4 * 64 * 256];       // proj weights [p][cout][cin] hi
__device__ __nv_bfloat16 g_Wplo[4 * 64 * 256];
__device__ __nv_bfloat16 g_Wfhi[256 * 128];          // fire weights [cout][cf] hi
__device__ __nv_bfloat16 g_Wflo[256 * 128];

#define SW128(x) ((x) ^ (((x) >> 3) & 0x70))
#define L2E 1.4426950408889634f

__device__ __forceinline__ uint32_t smem_to_u32(const void* p) {
    uint32_t a;
    asm("{ .reg .u64 t; cvta.to.shared.u64 t, %1; cvt.u32.u64 %0, t; }" : "=r"(a) : "l"(p));
    return a;
}
__device__ __forceinline__ uint32_t bf16pack2(float a, float b) {
    return (uint32_t)__bfloat16_as_ushort(__float2bfloat16_rn(a)) |
           ((uint32_t)__bfloat16_as_ushort(__float2bfloat16_rn(b)) << 16);
}
__device__ __forceinline__ void ldsm4(uint32_t r[4], uint32_t addr) {
    asm volatile("ldmatrix.sync.aligned.m8n8.x4.shared.b16 {%0,%1,%2,%3}, [%4];"
        : "=r"(r[0]), "=r"(r[1]), "=r"(r[2]), "=r"(r[3]) : "r"(addr));
}
__device__ __forceinline__ void ldsm4t(uint32_t r[4], uint32_t addr) {
    asm volatile("ldmatrix.sync.aligned.m8n8.x4.trans.shared.b16 {%0,%1,%2,%3}, [%4];"
        : "=r"(r[0]), "=r"(r[1]), "=r"(r[2]), "=r"(r[3]) : "r"(addr));
}
__device__ __forceinline__ void mma16816(float* d, const uint32_t* a, const uint32_t* b) {
    asm volatile("mma.sync.aligned.m16n8k16.row.col.f32.bf16.bf16.f32 "
        "{%0,%1,%2,%3}, {%4,%5,%6,%7}, {%8,%9}, {%0,%1,%2,%3};"
        : "+f"(d[0]), "+f"(d[1]), "+f"(d[2]), "+f"(d[3])
        : "r"(a[0]), "r"(a[1]), "r"(a[2]), "r"(a[3]), "r"(b[0]), "r"(b[1]));
}
__device__ __forceinline__ void cp_async16(uint32_t dst, const void* src) {
    asm volatile("cp.async.cg.shared.global [%0], [%1], 16;" :: "r"(dst), "l"(src) : "memory");
}
__device__ __forceinline__ float ex2(float x) {
    float y;
    asm("ex2.approx.f32 %0, %1;" : "=f"(y) : "f"(x));
    return y;
}
// split 8 fp32 -> 16B hi + 16B lo bf16
__device__ __forceinline__ void split8(float4 a, float4 b, uint4& hi, uint4& lo) {
    float v[8] = {a.x, a.y, a.z, a.w, b.x, b.y, b.z, b.w};
    uint32_t hp[4], lp[4];
    #pragma unroll
    for (int i = 0; i < 4; ++i) {
        __nv_bfloat16 h0 = __float2bfloat16_rn(v[2*i]);
        __nv_bfloat16 h1 = __float2bfloat16_rn(v[2*i+1]);
        hp[i] = (uint32_t)__bfloat16_as_ushort(h0) | ((uint32_t)__bfloat16_as_ushort(h1) << 16);
        lp[i] = bf16pack2(v[2*i] - __bfloat162float(h0), v[2*i+1] - __bfloat162float(h1));
    }
    hi = make_uint4(hp[0], hp[1], hp[2], hp[3]);
    lo = make_uint4(lp[0], lp[1], lp[2], lp[3]);
}

// ---------------------------------------------------------------------------
// Kernel 0: split all weights to bf16 hi/lo (q weights scaled by log2e).
// ---------------------------------------------------------------------------
__global__ __launch_bounds__(256) void wsplit_kernel(
    const float* __restrict__ Wqk, const float* __restrict__ Wkl,
    const float* __restrict__ Wkf, const float* __restrict__ Wv,
    const float* __restrict__ Wfire)
{
    int gid = blockIdx.x * 256 + threadIdx.x;
    float v;
    __nv_bfloat16 *dh, *dl;
    if (gid < 65536) {
        int p = gid >> 14, i = gid & 16383;
        const float* W = (p == 0) ? Wqk : (p == 1) ? Wkl : (p == 2) ? Wkf : Wv;
        v = W[i];
        if (p == 0) v *= L2E;
        dh = g_Wphi + gid; dl = g_Wplo + gid;
    } else {
        int i = gid - 65536;
        v = Wfire[i];
        dh = g_Wfhi + i; dl = g_Wflo + i;
    }
    __nv_bfloat16 h = __float2bfloat16_rn(v);
    *dh = h;
    *dl = __float2bfloat16_rn(v - __bfloat162float(h));
}

// ---------------------------------------------------------------------------
// Kernel 1: HMMA projections. grid(32 hw-tiles, B, 4 proj), block 256.
// ---------------------------------------------------------------------------
__global__ __launch_bounds__(256) void proj_kernel(
    const float* __restrict__ last, const float* __restrict__ cur, const float* __restrict__ fut,
    const float* __restrict__ bqk, const float* __restrict__ bkl,
    const float* __restrict__ bkf, const float* __restrict__ bv)
{
    __shared__ __align__(1024) uint8_t sm[49152];
    const uint32_t u = smem_to_u32(sm);

    const int tile = blockIdx.x, b = blockIdx.y, p = blockIdx.z;
    const float* X    = (p == 1) ? last : (p == 2) ? fut : cur;
    const float* bias = (p == 0) ? bqk : (p == 1) ? bkl : (p == 2) ? bkf : bv;
    const __nv_bfloat16* Wh = g_Wphi + p * 16384;
    const __nv_bfloat16* Wl = g_Wplo + p * 16384;
    const float* Xb = X + (size_t)b * CC * HWN + tile * 128;

    const int t = threadIdx.x, w = t >> 5, lane = t & 31;
    const int g = lane >> 3, r = lane & 7;

    float C[8][4];
    #pragma unroll
    for (int i = 0; i < 8; ++i)
        #pragma unroll
        for (int j = 0; j < 4; ++j) C[i][j] = 0.f;

    const uint32_t xbase = u + ((w & 4) ? 16384u : 0u);
    const uint32_t mloc  = (uint32_t)(w & 3) * 32u;

    for (int kc = 0; kc < 4; ++kc) {
        __syncthreads();
        #pragma unroll
        for (int pp = 0; pp < 2; ++pp) {
            int idx = t + pp * 256;
            int row = idx >> 3, c16 = idx & 7;
            uint32_t dst = SW128((uint32_t)(row * 128 + c16 * 16));
            *(uint4*)(sm + 32768 + dst) = *(const uint4*)((const uint8_t*)(Wh + row * 256 + kc * 64) + c16 * 16);
            *(uint4*)(sm + 40960 + dst) = *(const uint4*)((const uint8_t*)(Wl + row * 256 + kc * 64) + c16 * 16);
        }
        #pragma unroll
        for (int pp = 0; pp < 4; ++pp) {
            int idx = t + pp * 256;
            int row = idx >> 4, col8 = (idx & 15) * 8;
            const float* src = Xb + (size_t)(kc * 64 + row) * HWN + col8;
            float4 u0 = *(const float4*)src;
            float4 u1 = *(const float4*)(src + 4);
            uint4 hi, lo;
            split8(u0, u1, hi, lo);
            int half = col8 >> 6;
            uint32_t off = SW128((uint32_t)(row * 128 + (col8 & 63) * 2));
            *(uint4*)(sm + half * 16384 + off)        = hi;
            *(uint4*)(sm + half * 16384 + 8192 + off) = lo;
        }
        __syncthreads();

        #pragma unroll
        for (int s = 0; s < 4; ++s) {
            uint32_t aoff = SW128((uint32_t)((16 * s + (g >> 1) * 8 + r) * 128) + mloc + (uint32_t)(g & 1) * 16);
            uint32_t ah[4], al[4];
            ldsm4t(ah, xbase + aoff);
            ldsm4t(al, xbase + 8192 + aoff);
            #pragma unroll
            for (int jp = 0; jp < 4; ++jp) {
                uint32_t boff = SW128((uint32_t)((16 * jp + (g >> 1) * 8 + r) * 128 + (g & 1) * 16 + 32 * s));
                uint32_t bh[4], bl[4];
                ldsm4(bh, u + 32768 + boff);
                ldsm4(bl, u + 40960 + boff);
                mma16816(C[2*jp],   ah, bh + 0);
                mma16816(C[2*jp+1], ah, bh + 2);
                mma16816(C[2*jp],   ah, bl + 0);
                mma16816(C[2*jp+1], ah, bl + 2);
                mma16816(C[2*jp],   al, bh + 0);
                mma16816(C[2*jp+1], al, bh + 2);
            }
        }
    }

    __nv_bfloat16 *oh, *ol;
    if (p == 0)      { oh = g_qhi + (size_t)b * HWN * C4;        ol = g_qlo + (size_t)b * HWN * C4; }
    else if (p == 1) { oh = g_khi + (size_t)b * HWN * C4;        ol = g_klo + (size_t)b * HWN * C4; }
    else if (p == 2) { oh = g_khi + (size_t)(BB + b) * HWN * C4; ol = g_klo + (size_t)(BB + b) * HWN * C4; }
    else             { oh = g_vhi + (size_t)b * HWN * C4;        ol = g_vlo + (size_t)b * HWN * C4; }

    const float bscale = (p == 0) ? L2E : 1.0f;
    const int hw0 = tile * 128 + w * 16 + (lane >> 2);
    #pragma unroll
    for (int j = 0; j < 8; ++j) {
        int n = 8 * j + 2 * (lane & 3);
        float b0 = bias[n] * bscale, b1 = bias[n + 1] * bscale;
        float v0 = C[j][0] + b0, v1 = C[j][1] + b1;
        float v2 = C[j][2] + b0, v3 = C[j][3] + b1;
        __nv_bfloat16 h0 = __float2bfloat16_rn(v0), h1 = __float2bfloat16_rn(v1);
        __nv_bfloat16 h2 = __float2bfloat16_rn(v2), h3 = __float2bfloat16_rn(v3);
        *(uint32_t*)(oh + (size_t)hw0 * C4 + n) =
            (uint32_t)__bfloat16_as_ushort(h0) | ((uint32_t)__bfloat16_as_ushort(h1) << 16);
        *(uint32_t*)(oh + (size_t)(hw0 + 8) * C4 + n) =
            (uint32_t)__bfloat16_as_ushort(h2) | ((uint32_t)__bfloat16_as_ushort(h3) << 16);
        *(uint32_t*)(ol + (size_t)hw0 * C4 + n) =
            bf16pack2(v0 - __bfloat162float(h0), v1 - __bfloat162float(h1));
        *(uint32_t*)(ol + (size_t)(hw0 + 8) * C4 + n) =
            bf16pack2(v2 - __bfloat162float(h2), v3 - __bfloat162float(h3));
    }
}

// ---------------------------------------------------------------------------
// Kernel 2: mma.sync bf16 flash attention. grid(32, B, 2), block 256, occ 2.
// 3-stage cp.async ring (96KB), ONE sync/iter, quadrant-fused mainloop:
// per 16-key quadrant: GEMM1(24 mma) -> exp(8) -> GEMM2(24 mma); ptxas
// overlaps quadrant q's exp with q+1's GEMM1.
// ---------------------------------------------------------------------------
__global__ void __launch_bounds__(256, 2) attn_kernel()
{
    extern __shared__ __align__(1024) uint8_t smem[];
    const uint32_t u_base = smem_to_u32(smem);

    const int qt = blockIdx.x, b = blockIdx.y, side = blockIdx.z;
    const int q0c = qt * QT;
    const int t = threadIdx.x, w = t >> 5, lane = t & 31;
    const int g = lane >> 3, r = lane & 7;

    const uint8_t* gq_hi = (const uint8_t*)(g_qhi + (size_t)b * HWN * C4);
    const uint8_t* gq_lo = (const uint8_t*)(g_qlo + (size_t)b * HWN * C4);
    const uint8_t* gk_hi = (const uint8_t*)(g_khi + (size_t)(side * BB + b) * HWN * C4);
    const uint8_t* gk_lo = (const uint8_t*)(g_klo + (size_t)(side * BB + b) * HWN * C4);
    const uint8_t* gv_hi = (const uint8_t*)(g_vhi + (size_t)b * HWN * C4);
    const uint8_t* gv_lo = (const uint8_t*)(g_vlo + (size_t)b * HWN * C4);

    auto issue_tile = [&](int it) {
        const int k0 = it * 64;
        const uint32_t stage = u_base + (uint32_t)(it % 3) * 32768u;
        #pragma unroll
        for (int pp = 0; pp < 8; ++pp) {
            int idx = t + pp * 256;          // 0..2047
            int arr = idx >> 9;              // 0:KHI 1:KLO 2:VHI 3:VLO
            int sl  = idx & 511;
            int row = sl >> 3, cb = (sl & 7) * 16;
            uint32_t dst = stage + (uint32_t)arr * 8192 + SW128((uint32_t)(row * 128 + cb));
            size_t go = ((size_t)(k0 + row) * C4) * 2 + cb;
            const uint8_t* src;
            if (arr == 0)      src = gk_hi + go;
            else if (arr == 1) src = gk_lo + go;
            else if (arr == 2) src = gv_hi + go;
            else               src = gv_lo + go;
            cp_async16(dst, src);
        }
        asm volatile("cp.async.commit_group;" ::: "memory");
    };

    // prologue: tiles 0,1 in flight; Q staged through stage-2 area
    issue_tile(0);
    issue_tile(1);

    #pragma unroll
    for (int pp = 0; pp < 4; ++pp) {
        int idx = t + pp * 256;
        int row = idx >> 3, cb = (idx & 7) * 16;
        uint32_t sw = SW128((uint32_t)(row * 128 + cb));
        size_t go = ((size_t)(q0c + row) * C4) * 2 + cb;
        *(uint4*)(smem + 65536 + sw) = *(const uint4*)(gq_hi + go);
        *(uint4*)(smem + 81920 + sw) = *(const uint4*)(gq_lo + go);
    }
    __syncthreads();

    uint32_t qhi[4][4], qlo[4][4];
    #pragma unroll
    for (int s = 0; s < 4; ++s) {
        uint32_t off = SW128((uint32_t)((16 * w + (g & 1) * 8 + r) * 128 + (g >> 1) * 16 + 32 * s));
        ldsm4(qhi[s], u_base + 65536 + off);
        ldsm4(qlo[s], u_base + 81920 + off);
    }
    __syncthreads();   // all Q frags read -> stage 2 reusable

    float O[8][4];
    #pragma unroll
    for (int i = 0; i < 8; ++i)
        #pragma unroll
        for (int j = 0; j < 4; ++j) O[i][j] = 0.f;
    float lsum0 = 0.f, lsum1 = 0.f;

    for (int it = 0; it < 64; ++it) {
        if (it < 63) { asm volatile("cp.async.wait_group 1;" ::: "memory"); }
        else         { asm volatile("cp.async.wait_group 0;" ::: "memory"); }
        __syncthreads();                 // tile it ready AND stage (it+2)%3 drained
        if (it < 62) issue_tile(it + 2);

        const uint32_t stage = u_base + (uint32_t)(it % 3) * 32768u;
        const uint32_t u_khi = stage, u_klo = stage + 8192;
        const uint32_t u_vhi = stage + 16384, u_vlo = stage + 24576;

        #pragma unroll
        for (int jp = 0; jp < 4; ++jp) {
            // GEMM1 quadrant: S(16q x 16k) = Qhi.Khi + Qhi.Klo + Qlo.Khi
            float S0[4] = {0.f, 0.f, 0.f, 0.f};
            float S1[4] = {0.f, 0.f, 0.f, 0.f};
            #pragma unroll
            for (int s = 0; s < 4; ++s) {
                uint32_t koff = SW128((uint32_t)((jp * 16 + (g >> 1) * 8 + r) * 128 + (g & 1) * 16 + 32 * s));
                uint32_t kh[4], kl[4];
                ldsm4(kh, u_khi + koff);
                ldsm4(kl, u_klo + koff);
                mma16816(S0, qhi[s], kh + 0);
                mma16816(S1, qhi[s], kh + 2);
                mma16816(S0, qhi[s], kl + 0);
                mma16816(S1, qhi[s], kl + 2);
                mma16816(S0, qlo[s], kh + 0);
                mma16816(S1, qlo[s], kh + 2);
            }

            // exp2 quadrant, row-sum accum, P hi/lo repack
            uint32_t phi[4], plo[4];
            {
                float e0 = ex2(S0[0]), e1 = ex2(S0[1]), e2 = ex2(S0[2]), e3 = ex2(S0[3]);
                lsum0 += e0 + e1; lsum1 += e2 + e3;
                __nv_bfloat16 h0 = __float2bfloat16_rn(e0), h1 = __float2bfloat16_rn(e1);
                __nv_bfloat16 h2 = __float2bfloat16_rn(e2), h3 = __float2bfloat16_rn(e3);
                phi[0] = (uint32_t)__bfloat16_as_ushort(h0) | ((uint32_t)__bfloat16_as_ushort(h1) << 16);
                phi[1] = (uint32_t)__bfloat16_as_ushort(h2) | ((uint32_t)__bfloat16_as_ushort(h3) << 16);
                plo[0] = bf16pack2(e0 - __bfloat162float(h0), e1 - __bfloat162float(h1));
                plo[1] = bf16pack2(e2 - __bfloat162float(h2), e3 - __bfloat162float(h3));
                float f0 = ex2(S1[0]), f1 = ex2(S1[1]), f2 = ex2(S1[2]), f3 = ex2(S1[3]);
                lsum0 += f0 + f1; lsum1 += f2 + f3;
                __nv_bfloat16 j0 = __float2bfloat16_rn(f0), j1 = __float2bfloat16_rn(f1);
                __nv_bfloat16 j2 = __float2bfloat16_rn(f2), j3 = __float2bfloat16_rn(f3);
                phi[2] = (uint32_t)__bfloat16_as_ushort(j0) | ((uint32_t)__bfloat16_as_ushort(j1) << 16);
                phi[3] = (uint32_t)__bfloat16_as_ushort(j2) | ((uint32_t)__bfloat16_as_ushort(j3) << 16);
                plo[2] = bf16pack2(f0 - __bfloat162float(j0), f1 - __bfloat162float(j1));
                plo[3] = bf16pack2(f2 - __bfloat162float(j2), f3 - __bfloat162float(j3));
            }

            // GEMM2 quadrant: O += Phi.Vhi + Phi.Vlo + Plo.Vhi  (keys 16jp..+15)
            #pragma unroll
            for (int j = 0; j < 4; ++j) {
                uint32_t voff = SW128((uint32_t)((16 * jp + (g & 1) * 8 + r) * 128 + 32 * j + (g >> 1) * 16));
                uint32_t vh[4], vl[4];
                ldsm4t(vh, u_vhi + voff);
                ldsm4t(vl, u_vlo + voff);
                mma16816(O[2*j],   phi, vh + 0);
                mma16816(O[2*j+1], phi, vh + 2);
                mma16816(O[2*j],   phi, vl + 0);
                mma16816(O[2*j+1], phi, vl + 2);
                mma16816(O[2*j],   plo, vh + 0);
                mma16816(O[2*j+1], plo, vh + 2);
            }
        }
    }

    // normalize, split hi/lo, write fused bf16
    lsum0 += __shfl_xor_sync(0xffffffffu, lsum0, 1);
    lsum0 += __shfl_xor_sync(0xffffffffu, lsum0, 2);
    lsum1 += __shfl_xor_sync(0xffffffffu, lsum1, 1);
    lsum1 += __shfl_xor_sync(0xffffffffu, lsum1, 2);
    const float i0 = 1.0f / lsum0, i1 = 1.0f / lsum1;

    const int qr0 = q0c + 16 * w + (lane >> 2);
    const int qr1 = qr0 + 8;
    __nv_bfloat16* fh = g_fhi + (size_t)b * HWN * 128 + side * 64;
    __nv_bfloat16* fl = g_flo + (size_t)b * HWN * 128 + side * 64;
    #pragma unroll
    for (int tt = 0; tt < 8; ++tt) {
        int ct = 8 * tt + 2 * (lane & 3);
        float v0 = O[tt][0] * i0, v1 = O[tt][1] * i0;
        float v2 = O[tt][2] * i1, v3 = O[tt][3] * i1;
        __nv_bfloat16 h0 = __float2bfloat16_rn(v0), h1 = __float2bfloat16_rn(v1);
        __nv_bfloat16 h2 = __float2bfloat16_rn(v2), h3 = __float2bfloat16_rn(v3);
        *(uint32_t*)(fh + (size_t)qr0 * 128 + ct) =
            (uint32_t)__bfloat16_as_ushort(h0) | ((uint32_t)__bfloat16_as_ushort(h1) << 16);
        *(uint32_t*)(fh + (size_t)qr1 * 128 + ct) =
            (uint32_t)__bfloat16_as_ushort(h2) | ((uint32_t)__bfloat16_as_ushort(h3) << 16);
        *(uint32_t*)(fl + (size_t)qr0 * 128 + ct) =
            bf16pack2(v0 - __bfloat162float(h0), v1 - __bfloat162float(h1));
        *(uint32_t*)(fl + (size_t)qr1 * 128 + ct) =
            bf16pack2(v2 - __bfloat162float(h2), v3 - __bfloat162float(h3));
    }
}

// ---------------------------------------------------------------------------
// Kernel 3: HMMA fire conv + BN + residual + ReLU. grid(32, 4, B), block 256.
// Two cp.async groups: W + F-half0 first -> compute kh=0 overlaps F-half1.
// ---------------------------------------------------------------------------
__global__ void __launch_bounds__(256, 2) fire_kernel(
    const float* __restrict__ cur,
    const float* __restrict__ bfire,
    const float* __restrict__ gamma, const float* __restrict__ beta,
    const float* __restrict__ mean,  const float* __restrict__ var,
    float* __restrict__ out)
{
    extern __shared__ __align__(1024) uint8_t smem[];
    const uint32_t u = smem_to_u32(smem);

    const int tile = blockIdx.x, rt = blockIdx.y, b = blockIdx.z;
    const int r0 = rt * 64, col0 = tile * 128;
    const int t = threadIdx.x, w = t >> 5, lane = t & 31;
    const int g = lane >> 3, r = lane & 7;

    // group A: W (both halves) + F cf-half 0
    #pragma unroll
    for (int pp = 0; pp < 8; ++pp) {
        int idx = t + pp * 256;
        int arr = idx >> 9;                  // 0:W0h 1:W0l 2:W1h 3:W1l
        int sl  = idx & 511;
        int row = sl >> 3, c16 = sl & 7;
        int khalf = arr >> 1;
        const __nv_bfloat16* src = ((arr & 1) ? g_Wflo : g_Wfhi) + (size_t)(r0 + row) * 128 + khalf * 64 + c16 * 8;
        cp_async16(u + (uint32_t)arr * 8192 + SW128((uint32_t)(row * 128 + c16 * 16)), src);
    }
    #pragma unroll
    for (int pp = 0; pp < 8; ++pp) {
        int idx = t + pp * 256;              // 0..2047 -> arr 0,1 (F0h,F0l)
        int arr = idx >> 10;
        int sl  = idx & 1023;
        int row = sl >> 3, c16 = sl & 7;
        const __nv_bfloat16* src = ((arr & 1) ? g_flo : g_fhi) +
            (size_t)b * HWN * 128 + (size_t)(col0 + row) * 128 + c16 * 8;
        cp_async16(u + 32768 + (uint32_t)arr * 16384 + SW128((uint32_t)(row * 128 + c16 * 16)), src);
    }
    asm volatile("cp.async.commit_group;" ::: "memory");
    // group B: F cf-half 1
    #pragma unroll
    for (int pp = 0; pp < 8; ++pp) {
        int idx = t + pp * 256;
        int arr = idx >> 10;                 // 0,1 -> F1h,F1l
        int sl  = idx & 1023;
        int row = sl >> 3, c16 = sl & 7;
        const __nv_bfloat16* src = ((arr & 1) ? g_flo : g_fhi) +
            (size_t)b * HWN * 128 + (size_t)(col0 + row) * 128 + 64 + c16 * 8;
        cp_async16(u + 65536 + (uint32_t)arr * 16384 + SW128((uint32_t)(row * 128 + c16 * 16)), src);
    }
    asm volatile("cp.async.commit_group;" ::: "memory");

    float C[8][4];
    #pragma unroll
    for (int i = 0; i < 8; ++i)
        #pragma unroll
        for (int j = 0; j < 4; ++j) C[i][j] = 0.f;

    const int nwbase = (w >> 2) * 64;
    asm volatile("cp.async.wait_group 1;" ::: "memory");
    __syncthreads();

    #pragma unroll
    for (int kh = 0; kh < 2; ++kh) {
        if (kh == 1) {
            asm volatile("cp.async.wait_group 0;" ::: "memory");
            __syncthreads();
        }
        uint32_t wbase = u + (uint32_t)kh * 16384;
        uint32_t fbase = u + 32768 + (uint32_t)kh * 32768;
        #pragma unroll
        for (int s = 0; s < 4; ++s) {
            uint32_t aoff = SW128((uint32_t)(((w & 3) * 16 + (g & 1) * 8 + r) * 128 + (g >> 1) * 16 + 32 * s));
            uint32_t ah[4], al[4];
            ldsm4(ah, wbase + aoff);
            ldsm4(al, wbase + 8192 + aoff);
            #pragma unroll
            for (int nf = 0; nf < 4; ++nf) {
                uint32_t boff = SW128((uint32_t)((nwbase + 16 * nf + (g >> 1) * 8 + r) * 128 + (g & 1) * 16 + 32 * s));
                uint32_t bh[4], bl[4];
                ldsm4(bh, fbase + boff);
                ldsm4(bl, fbase + 16384 + boff);
                mma16816(C[2*nf],   ah, bh + 0);
                mma16816(C[2*nf+1], ah, bh + 2);
                mma16816(C[2*nf],   ah, bl + 0);
                mma16816(C[2*nf+1], ah, bl + 2);
                mma16816(C[2*nf],   al, bh + 0);
                mma16816(C[2*nf+1], al, bh + 2);
            }
        }
    }

    const int m0 = r0 + (w & 3) * 16 + (lane >> 2);
    const int m1 = m0 + 8;
    const float inv0 = gamma[m0] * rsqrtf(var[m0] + 1e-5f);
    const float sh0  = beta[m0] - mean[m0] * inv0;
    const float bb0  = bfire[m0];
    const float inv1 = gamma[m1] * rsqrtf(var[m1] + 1e-5f);
    const float sh1  = beta[m1] - mean[m1] * inv1;
    const float bb1  = bfire[m1];

    const float* curb = cur + (size_t)b * CC * HWN;
    float* outb = out + (size_t)b * CC * HWN;
    const int hwb = col0 + nwbase;
    #pragma unroll
    for (int j = 0; j < 8; ++j) {
        int n = hwb + 8 * j + 2 * (lane & 3);
        float2 c0 = *(const float2*)&curb[(size_t)m0 * HWN + n];
        float2 c1 = *(const float2*)&curb[(size_t)m1 * HWN + n];
        float2 o0, o1;
        o0.x = fmaxf(c0.x + (C[j][0] + bb0) * inv0 + sh0, 0.f);
        o0.y = fmaxf(c0.y + (C[j][1] + bb0) * inv0 + sh0, 0.f);
        o1.x = fmaxf(c1.x + (C[j][2] + bb1) * inv1 + sh1, 0.f);
        o1.y = fmaxf(c1.y + (C[j][3] + bb1) * inv1 + sh1, 0.f);
        *(float2*)&outb[(size_t)m0 * HWN + n] = o0;
        *(float2*)&outb[(size_t)m1 * HWN + n] = o1;
    }
}

// ---------------------------------------------------------------------------
extern "C" void kernel_launch(void* const* d_in, const int* in_sizes, int n_in,
                              void* d_out, int out_size)
{
    const float* last  = (const float*)d_in[0];
    const float* cur   = (const float*)d_in[1];
    const float* fut   = (const float*)d_in[2];
    const float* Wqk   = (const float*)d_in[3];
    const float* bqk   = (const float*)d_in[4];
    const float* Wkl   = (const float*)d_in[5];
    const float* bkl   = (const float*)d_in[6];
    const float* Wkf   = (const float*)d_in[7];
    const float* bkf   = (const float*)d_in[8];
    const float* Wv    = (const float*)d_in[9];
    const float* bv    = (const float*)d_in[10];
    const float* Wfire = (const float*)d_in[11];
    const float* bfire = (const float*)d_in[12];
    const float* gamma = (const float*)d_in[13];
    const float* beta  = (const float*)d_in[14];
    const float* mean  = (const float*)d_in[15];
    const float* var   = (const float*)d_in[16];

    cudaFuncSetAttribute(attn_kernel, cudaFuncAttributeMaxDynamicSharedMemorySize, 98304);
    cudaFuncSetAttribute(fire_kernel, cudaFuncAttributeMaxDynamicSharedMemorySize, 98304);

    wsplit_kernel<<<384, 256>>>(Wqk, Wkl, Wkf, Wv, Wfire);
    proj_kernel<<<dim3(32, BB, 4), 256>>>(last, cur, fut, bqk, bkl, bkf, bv);
    attn_kernel<<<dim3(32, BB, 2), 256, 98304>>>();
    fire_kernel<<<dim3(32, 4, BB), 256, 98304>>>(cur, bfire, gamma, beta, mean, var, (float*)d_out);
}